// round 10
// baseline (speedup 1.0000x reference)
#include <cuda_runtime.h>
#include <cuda_fp16.h>
#include <math.h>
#include <stdint.h>

#define B_  2
#define S_  2048
#define D_  1024
#define H_  16
#define DK_ 64
#define SCALE_ 0.125f
#define LOG2E_ 1.44269504f
#define TNEG_ (-86562.0f)   // -60000 * log2(e)

// ---------------- scratch ----------------
__device__ __half   g_xh[B_ * S_ * D_];
__device__ uint8_t  g_x8[B_ * S_ * D_ * 2];        // packed [h8|l8] per 32-elem k-block
__device__ __half   g_wqkvh[3 * D_ * D_];
__device__ uint8_t  g_wqkv8[3 * D_ * D_ * 2];
__device__ __half   g_wouth[D_ * D_];
__device__ uint8_t  g_wout8[D_ * D_ * 2];
__device__ __half   g_qkvh[B_ * S_ * 3 * D_];
__device__ __half   g_qkvl[B_ * S_ * 3 * D_];
__device__ __half   g_cth[B_ * S_ * D_];
__device__ uint8_t  g_ct8[B_ * S_ * D_ * 2];

// ================= helpers =================
__device__ __forceinline__ uint32_t smem_u32(const void* p) {
    uint32_t a;
    asm("{ .reg .u64 t; cvta.to.shared.u64 t, %1; cvt.u32.u64 %0, t; }" : "=r"(a) : "l"(p));
    return a;
}
#define CP16(dst, src) asm volatile("cp.async.cg.shared.global [%0], [%1], 16;" :: "r"(dst), "l"(src) : "memory")
#define CP_COMMIT()    asm volatile("cp.async.commit_group;" ::: "memory")
#define CP_WAIT0()     asm volatile("cp.async.wait_group 0;" ::: "memory")

__device__ __forceinline__ void ldsm4(uint32_t* r, uint32_t addr) {
    asm volatile("ldmatrix.sync.aligned.m8n8.x4.shared.b16 {%0,%1,%2,%3}, [%4];"
        : "=r"(r[0]), "=r"(r[1]), "=r"(r[2]), "=r"(r[3]) : "r"(addr));
}
__device__ __forceinline__ void ldsm4t(uint32_t* r, uint32_t addr) {
    asm volatile("ldmatrix.sync.aligned.m8n8.x4.trans.shared.b16 {%0,%1,%2,%3}, [%4];"
        : "=r"(r[0]), "=r"(r[1]), "=r"(r[2]), "=r"(r[3]) : "r"(addr));
}
// fp16 x fp16 -> fp32
__device__ __forceinline__ void mma16816(float* d, const uint32_t* a, const uint32_t* b) {
    asm volatile("mma.sync.aligned.m16n8k16.row.col.f32.f16.f16.f32 "
        "{%0,%1,%2,%3}, {%4,%5,%6,%7}, {%8,%9}, {%0,%1,%2,%3};"
        : "+f"(d[0]), "+f"(d[1]), "+f"(d[2]), "+f"(d[3])
        : "r"(a[0]), "r"(a[1]), "r"(a[2]), "r"(a[3]), "r"(b[0]), "r"(b[1]));
}
// e4m3 x e4m3 -> fp32, K=32
__device__ __forceinline__ void mma16832f8(float* d, const uint32_t* a, const uint32_t* b) {
    asm volatile("mma.sync.aligned.m16n8k32.row.col.f32.e4m3.e4m3.f32 "
        "{%0,%1,%2,%3}, {%4,%5,%6,%7}, {%8,%9}, {%0,%1,%2,%3};"
        : "+f"(d[0]), "+f"(d[1]), "+f"(d[2]), "+f"(d[3])
        : "r"(a[0]), "r"(a[1]), "r"(a[2]), "r"(a[3]), "r"(b[0]), "r"(b[1]));
}
__device__ __forceinline__ float ex2(float x) {
    float y; asm("ex2.approx.ftz.f32 %0, %1;" : "=f"(y) : "f"(x)); return y;
}
// fp16 hi/lo split, UNSCALED lo (single fp32 accumulator downstream)
__device__ __forceinline__ void split2h(float a, float b, uint32_t& hi, uint32_t& lo) {
    __half ha = __float2half_rn(a), hb = __float2half_rn(b);
    hi = (uint32_t)__half_as_ushort(ha) | ((uint32_t)__half_as_ushort(hb) << 16);
    __half la = __float2half_rn(a - __half2float(ha));
    __half lb = __float2half_rn(b - __half2float(hb));
    lo = (uint32_t)__half_as_ushort(la) | ((uint32_t)__half_as_ushort(lb) << 16);
}
// pack two floats to e4m3 pair; elem0 -> low byte (memory order)
__device__ __forceinline__ unsigned short cvt_e4m3x2(float e0, float e1) {
    unsigned short r;
    asm("cvt.rn.satfinite.e4m3x2.f32 %0, %1, %2;" : "=h"(r) : "f"(e1), "f"(e0));
    return r;
}

// ================= split fp32 -> (fp16 hi) + packed fp8 (h8|l8) =================
// p8 layout: row-major rows of 2K bytes; k-block j (32 elems): h8 at row*2K + j*64 + (k&31), l8 at +32
__global__ void split_pack(const float* __restrict__ in, __half* __restrict__ h16,
                           uint8_t* __restrict__ p8, float s8, int K, int n4) {
    int i = blockIdx.x * blockDim.x + threadIdx.x;
    if (i >= n4) return;
    float4 v = ((const float4*)in)[i];
    float f[4] = {v.x, v.y, v.z, v.w};
    __half h[4]; float lo[4];
    #pragma unroll
    for (int j = 0; j < 4; j++) {
        h[j] = __float2half_rn(f[j]);
        lo[j] = f[j] - __half2float(h[j]);
    }
    ((__half2*)h16)[i * 2 + 0] = __halves2half2(h[0], h[1]);
    ((__half2*)h16)[i * 2 + 1] = __halves2half2(h[2], h[3]);

    float ls = s8 * 4096.0f;
    uint32_t h8 = (uint32_t)cvt_e4m3x2(f[0] * s8, f[1] * s8)
                | ((uint32_t)cvt_e4m3x2(f[2] * s8, f[3] * s8) << 16);
    uint32_t l8 = (uint32_t)cvt_e4m3x2(lo[0] * ls, lo[1] * ls)
                | ((uint32_t)cvt_e4m3x2(lo[2] * ls, lo[3] * ls) << 16);
    int k0 = i * 4;
    int row = k0 / K, k = k0 % K;
    size_t base = (size_t)row * 2 * K + ((k >> 5) << 6) + (k & 31);
    *(uint32_t*)(p8 + base) = h8;
    *(uint32_t*)(p8 + base + 32) = l8;
}

// ================= GEMM: fp16 hi + fp8 cross =================
// 128x128 tile, BK=32 (k32 chunks), 256 threads, 2-stage cp.async.
// Tiles per stage: Ah(fp16 64B/row), A8([h8|l8] 64B/row), Bh, B8 — stride 80.
#define GSTRIDE_B 80
#define GTILE_B (128 * GSTRIDE_B)       // 10240
#define GSTAGE_B (4 * GTILE_B)          // 40960
#define MERGE8_ (1.0f / 65536.0f)

__global__ __launch_bounds__(256)
void gemm_mma(const __half* __restrict__ Ah, const uint8_t* __restrict__ A8,
              const __half* __restrict__ Bh, const uint8_t* __restrict__ B8,
              float* __restrict__ Cf, __half* __restrict__ Ch, __half* __restrict__ Cl,
              int N, int K, int split_out)
{
    extern __shared__ char sm[];
    const int tid = threadIdx.x, wid = tid >> 5, lane = tid & 31;
    const int wm = wid & 3, wn = wid >> 2;   // warp = 32 rows x 64 cols
    uint32_t sbase = smem_u32(sm);

    const char* gt[4];
    gt[0] = (const char*)(Ah + (size_t)blockIdx.y * 128 * K);
    gt[1] = (const char*)(A8 + (size_t)blockIdx.y * 128 * 2 * K);
    gt[2] = (const char*)(Bh + (size_t)blockIdx.x * 128 * K);
    gt[3] = (const char*)(B8 + (size_t)blockIdx.x * 128 * 2 * K);

    float acc[2][8][4] = {};
    float acc2[2][8][4] = {};

    const int lrow = tid >> 2, lcol = tid & 3;   // 64 rows/pass, 4 chunks/row
    auto load_stage = [&](int j) {
        uint32_t sb = sbase + (j & 1) * GSTAGE_B;
        #pragma unroll
        for (int t = 0; t < 4; t++) {
            const char* g = gt[t] + (size_t)j * 64;   // all tiles: 64B per k32 chunk
            uint32_t tb = sb + t * GTILE_B;
            #pragma unroll
            for (int i = 0; i < 2; i++) {
                int row = lrow + i * 64;
                CP16(tb + row * GSTRIDE_B + lcol * 16,
                     g + (size_t)row * 2 * K + lcol * 16);   // row stride = 2K bytes for all
            }
        }
    };

    load_stage(0); CP_COMMIT();
    const int NK = K / 32;

    const uint32_t arow = (lane & 15), acs = (lane >> 4) * 16;
    const uint32_t brow = (lane & 7) + (lane >> 4) * 8, bcs = ((lane >> 3) & 1) * 16;

    for (int j = 0; j < NK; j++) {
        CP_WAIT0();
        __syncthreads();
        if (j + 1 < NK) { load_stage(j + 1); CP_COMMIT(); }

        uint32_t sb = sbase + (j & 1) * GSTAGE_B;
        uint32_t tAh = sb + wm * 32 * GSTRIDE_B;
        uint32_t tA8 = tAh + GTILE_B;
        uint32_t tBh = sb + 2 * GTILE_B + wn * 64 * GSTRIDE_B;
        uint32_t tB8 = tBh + GTILE_B;

        // ---- fp16 hi terms (2 x k16) ----
        #pragma unroll
        for (int ks = 0; ks < 2; ks++) {
            uint32_t ah[2][4];
            #pragma unroll
            for (int mt = 0; mt < 2; mt++)
                ldsm4(ah[mt], tAh + (mt * 16 + arow) * GSTRIDE_B + ks * 32 + acs);
            #pragma unroll
            for (int np = 0; np < 4; np++) {
                uint32_t bh[4];
                ldsm4(bh, tBh + (np * 16 + brow) * GSTRIDE_B + ks * 32 + bcs);
                #pragma unroll
                for (int mt = 0; mt < 2; mt++) {
                    mma16816(acc[mt][2 * np],     ah[mt], &bh[0]);
                    mma16816(acc[mt][2 * np + 1], ah[mt], &bh[2]);
                }
            }
        }
        // ---- fp8 cross terms (1 x k32) ----
        {
            uint32_t a8h[2][4], a8l[2][4];
            #pragma unroll
            for (int mt = 0; mt < 2; mt++) {
                ldsm4(a8h[mt], tA8 + (mt * 16 + arow) * GSTRIDE_B + acs);
                ldsm4(a8l[mt], tA8 + (mt * 16 + arow) * GSTRIDE_B + 32 + acs);
            }
            #pragma unroll
            for (int np = 0; np < 4; np++) {
                uint32_t b8h[4], b8l[4];
                ldsm4(b8h, tB8 + (np * 16 + brow) * GSTRIDE_B + bcs);
                ldsm4(b8l, tB8 + (np * 16 + brow) * GSTRIDE_B + 32 + bcs);
                #pragma unroll
                for (int mt = 0; mt < 2; mt++) {
                    mma16832f8(acc2[mt][2 * np],     a8h[mt], &b8l[0]);
                    mma16832f8(acc2[mt][2 * np],     a8l[mt], &b8h[0]);
                    mma16832f8(acc2[mt][2 * np + 1], a8h[mt], &b8l[2]);
                    mma16832f8(acc2[mt][2 * np + 1], a8l[mt], &b8h[2]);
                }
            }
        }
    }

    const int rb = blockIdx.y * 128 + wm * 32 + (lane >> 2);
    const int cb = blockIdx.x * 128 + wn * 64 + (lane & 3) * 2;
    #pragma unroll
    for (int mt = 0; mt < 2; mt++)
        #pragma unroll
        for (int half = 0; half < 2; half++) {
            int r = rb + mt * 16 + half * 8;
            #pragma unroll
            for (int nt = 0; nt < 8; nt++) {
                int c = cb + nt * 8;
                float v0 = acc[mt][nt][half * 2 + 0] + acc2[mt][nt][half * 2 + 0] * MERGE8_;
                float v1 = acc[mt][nt][half * 2 + 1] + acc2[mt][nt][half * 2 + 1] * MERGE8_;
                if (split_out) {
                    uint32_t hi, lo;
                    split2h(v0, v1, hi, lo);
                    *(uint32_t*)(Ch + (size_t)r * N + c) = hi;
                    *(uint32_t*)(Cl + (size_t)r * N + c) = lo;
                } else {
                    *(float2*)(Cf + (size_t)r * N + c) = make_float2(v0, v1);
                }
            }
        }
}

// ================= flash attention, fp16 3-term, fp32 accum =================
#define FSTRIDE_B 144
#define FTILE_B (64 * FSTRIDE_B)
#define FSTAGE_B (4 * FTILE_B)
#define FQ_OFF 0
#define FST_OFF (2 * FTILE_B)
#define FMS_OFF (FST_OFF + 2 * FSTAGE_B)
#define FSMEM_TOTAL (FMS_OFF + 128)

__global__ __launch_bounds__(128, 2)
void flash_mma(const __half* __restrict__ qh, const __half* __restrict__ ql,
               const unsigned char* __restrict__ mask,
               __half* __restrict__ cth, uint8_t* __restrict__ ct8)
{
    extern __shared__ char sm[];
    const int tid = threadIdx.x, wid = tid >> 5, lane = tid & 31;
    const int bh_ = blockIdx.y, b = bh_ >> 4, h = bh_ & 15;
    const int q0 = blockIdx.x * 64;
    uint32_t sbase = smem_u32(sm);
    const uint32_t QH = sbase + FQ_OFF, QL = QH + FTILE_B;
    const uint32_t STG = sbase + FST_OFF;

    const size_t rs = 3 * D_;
    const char* qbh = (const char*)(qh + ((size_t)b * S_ + q0) * rs + h * 64);
    const char* qbl = (const char*)(ql + ((size_t)b * S_ + q0) * rs + h * 64);
    const char* kbh = (const char*)(qh + (size_t)b * S_ * rs + D_ + h * 64);
    const char* kbl = (const char*)(ql + (size_t)b * S_ * rs + D_ + h * 64);
    const char* vbh = (const char*)(qh + (size_t)b * S_ * rs + 2 * D_ + h * 64);
    const char* vbl = (const char*)(ql + (size_t)b * S_ * rs + 2 * D_ + h * 64);

    auto load_kv = [&](int j) {
        uint32_t sb = STG + (j & 1) * FSTAGE_B;
        size_t gk = (size_t)j * 64 * rs * 2;
        #pragma unroll
        for (int i = 0; i < 4; i++) {
            int c = tid + i * 128;
            int row = c >> 3, col = c & 7;
            size_t go = gk + (size_t)row * rs * 2 + col * 16;
            uint32_t so = row * FSTRIDE_B + col * 16;
            CP16(sb + 0 * FTILE_B + so, kbh + go);
            CP16(sb + 1 * FTILE_B + so, kbl + go);
            CP16(sb + 2 * FTILE_B + so, vbh + go);
            CP16(sb + 3 * FTILE_B + so, vbl + go);
        }
    };
    auto store_mask = [&](int j) {
        if (tid < 16) {
            uint32_t v = *(const uint32_t*)(mask + (size_t)b * S_ + j * 64 + tid * 4);
            *(uint32_t*)(sm + FMS_OFF + (j & 1) * 64 + tid * 4) = v;
        }
    };

    #pragma unroll
    for (int i = 0; i < 4; i++) {
        int c = tid + i * 128;
        int row = c >> 3, col = c & 7;
        uint32_t so = row * FSTRIDE_B + col * 16;
        CP16(QH + so, qbh + (size_t)row * rs * 2 + col * 16);
        CP16(QL + so, qbl + (size_t)row * rs * 2 + col * 16);
    }
    load_kv(0); CP_COMMIT();
    store_mask(0);

    uint32_t qfh[4][4], qfl[4][4];
    float o[8][4] = {};
    float m0 = -1e30f, m1 = -1e30f, l0 = 0.0f, l1 = 0.0f;

    const uint32_t arow = (lane & 15), acs = (lane >> 4) * 16;
    const uint32_t brow = (lane & 7) + (lane >> 4) * 8, bcs = ((lane >> 3) & 1) * 16;

    for (int kt = 0; kt < S_ / 64; kt++) {
        CP_WAIT0();
        __syncthreads();
        if (kt == 0) {
            #pragma unroll
            for (int ks = 0; ks < 4; ks++) {
                ldsm4(qfh[ks], QH + (wid * 16 + arow) * FSTRIDE_B + ks * 32 + acs);
                ldsm4(qfl[ks], QL + (wid * 16 + arow) * FSTRIDE_B + ks * 32 + acs);
            }
        }
        if (kt + 1 < S_ / 64) { load_kv(kt + 1); CP_COMMIT(); store_mask(kt + 1); }

        uint32_t sb = STG + (kt & 1) * FSTAGE_B;
        uint32_t KH = sb, KL = sb + FTILE_B, VH = sb + 2 * FTILE_B, VL = sb + 3 * FTILE_B;

        // ---- S = Q K^T, 3-term fp16 -> fp32 ----
        float s[8][4] = {};
        #pragma unroll
        for (int ks = 0; ks < 4; ks++) {
            uint32_t kh[4][4], kl[4][4];
            #pragma unroll
            for (int np = 0; np < 4; np++) {
                ldsm4(kh[np], KH + (np * 16 + brow) * FSTRIDE_B + ks * 32 + bcs);
                ldsm4(kl[np], KL + (np * 16 + brow) * FSTRIDE_B + ks * 32 + bcs);
            }
            #pragma unroll
            for (int np = 0; np < 4; np++) {
                mma16816(s[2 * np],     qfh[ks], &kh[np][0]);
                mma16816(s[2 * np + 1], qfh[ks], &kh[np][2]);
                mma16816(s[2 * np],     qfh[ks], &kl[np][0]);
                mma16816(s[2 * np + 1], qfh[ks], &kl[np][2]);
                mma16816(s[2 * np],     qfl[ks], &kh[np][0]);
                mma16816(s[2 * np + 1], qfl[ks], &kh[np][2]);
            }
        }

        // ---- softmax (exp2 domain) ----
        const float CM = SCALE_ * LOG2E_;
        float rmax0 = -1e30f, rmax1 = -1e30f;
        #pragma unroll
        for (int nt = 0; nt < 8; nt++) {
            unsigned short mm = *(const unsigned short*)(sm + FMS_OFF + (kt & 1) * 64 + nt * 8 + (lane & 3) * 2);
            bool k0m = (mm & 0xFF) != 0, k1m = (mm >> 8) != 0;
            s[nt][0] = k0m ? TNEG_ : s[nt][0] * CM;
            s[nt][1] = k1m ? TNEG_ : s[nt][1] * CM;
            s[nt][2] = k0m ? TNEG_ : s[nt][2] * CM;
            s[nt][3] = k1m ? TNEG_ : s[nt][3] * CM;
            rmax0 = fmaxf(rmax0, fmaxf(s[nt][0], s[nt][1]));
            rmax1 = fmaxf(rmax1, fmaxf(s[nt][2], s[nt][3]));
        }
        rmax0 = fmaxf(rmax0, __shfl_xor_sync(0xffffffffu, rmax0, 1));
        rmax0 = fmaxf(rmax0, __shfl_xor_sync(0xffffffffu, rmax0, 2));
        rmax1 = fmaxf(rmax1, __shfl_xor_sync(0xffffffffu, rmax1, 1));
        rmax1 = fmaxf(rmax1, __shfl_xor_sync(0xffffffffu, rmax1, 2));
        float mn0 = fmaxf(m0, rmax0), mn1 = fmaxf(m1, rmax1);
        float cr0 = ex2(m0 - mn0), cr1 = ex2(m1 - mn1);
        m0 = mn0; m1 = mn1;
        float ps0 = 0.0f, ps1 = 0.0f;
        #pragma unroll
        for (int nt = 0; nt < 8; nt++) {
            s[nt][0] = ex2(s[nt][0] - mn0);
            s[nt][1] = ex2(s[nt][1] - mn0);
            s[nt][2] = ex2(s[nt][2] - mn1);
            s[nt][3] = ex2(s[nt][3] - mn1);
            ps0 += s[nt][0] + s[nt][1];
            ps1 += s[nt][2] + s[nt][3];
        }
        ps0 += __shfl_xor_sync(0xffffffffu, ps0, 1);
        ps0 += __shfl_xor_sync(0xffffffffu, ps0, 2);
        ps1 += __shfl_xor_sync(0xffffffffu, ps1, 1);
        ps1 += __shfl_xor_sync(0xffffffffu, ps1, 2);
        l0 = l0 * cr0 + ps0;
        l1 = l1 * cr1 + ps1;
        #pragma unroll
        for (int nt = 0; nt < 8; nt++) {
            o[nt][0] *= cr0; o[nt][1] *= cr0;
            o[nt][2] *= cr1; o[nt][3] *= cr1;
        }

        // P -> fp16 hi/lo (unscaled lo)
        uint32_t ph[4][4], pl[4][4];
        #pragma unroll
        for (int kp = 0; kp < 4; kp++) {
            split2h(s[2 * kp][0],     s[2 * kp][1],     ph[kp][0], pl[kp][0]);
            split2h(s[2 * kp][2],     s[2 * kp][3],     ph[kp][1], pl[kp][1]);
            split2h(s[2 * kp + 1][0], s[2 * kp + 1][1], ph[kp][2], pl[kp][2]);
            split2h(s[2 * kp + 1][2], s[2 * kp + 1][3], ph[kp][3], pl[kp][3]);
        }

        // ---- O += P V, 3-term fp16 -> fp32 ----
        #pragma unroll
        for (int kp = 0; kp < 4; kp++) {
            uint32_t vh[4][4], vl[4][4];
            uint32_t krow = kp * 16 + (lane & 15);
            uint32_t dbyte = (lane >> 4) * 16;
            #pragma unroll
            for (int dp = 0; dp < 4; dp++) {
                ldsm4t(vh[dp], VH + krow * FSTRIDE_B + dp * 32 + dbyte);
                ldsm4t(vl[dp], VL + krow * FSTRIDE_B + dp * 32 + dbyte);
            }
            #pragma unroll
            for (int dp = 0; dp < 4; dp++) {
                mma16816(o[2 * dp],     ph[kp], &vh[dp][0]);
                mma16816(o[2 * dp + 1], ph[kp], &vh[dp][2]);
                mma16816(o[2 * dp],     ph[kp], &vl[dp][0]);
                mma16816(o[2 * dp + 1], ph[kp], &vl[dp][2]);
                mma16816(o[2 * dp],     pl[kp], &vh[dp][0]);
                mma16816(o[2 * dp + 1], pl[kp], &vh[dp][2]);
            }
        }
    }

    // epilogue: ctx -> fp16 hi + packed fp8 (h8 scale 1, l8 scale 4096)
    float il0 = 1.0f / l0, il1 = 1.0f / l1;
    int r0 = q0 + wid * 16 + (lane >> 2);
    int cbase = h * 64 + (lane & 3) * 2;
    #pragma unroll
    for (int nt = 0; nt < 8; nt++) {
        int c = cbase + nt * 8;
        #pragma unroll
        for (int half = 0; half < 2; half++) {
            int r = r0 + half * 8;
            float v0 = o[nt][half * 2 + 0] * (half ? il1 : il0);
            float v1 = o[nt][half * 2 + 1] * (half ? il1 : il0);
            __half h0 = __float2half_rn(v0), h1 = __float2half_rn(v1);
            uint32_t hi = (uint32_t)__half_as_ushort(h0) | ((uint32_t)__half_as_ushort(h1) << 16);
            size_t idx = ((size_t)b * S_ + r) * D_ + c;
            *(uint32_t*)(cth + idx) = hi;
            float e0 = (v0 - __half2float(h0)) * 4096.0f;
            float e1 = (v1 - __half2float(h1)) * 4096.0f;
            size_t b8 = ((size_t)b * S_ + r) * 2048 + ((c >> 5) << 6) + (c & 31);
            *(unsigned short*)(ct8 + b8)      = cvt_e4m3x2(v0, v1);
            *(unsigned short*)(ct8 + b8 + 32) = cvt_e4m3x2(e0, e1);
        }
    }
}

// ---------------- launch ----------------
extern "C" void kernel_launch(void* const* d_in, const int* in_sizes, int n_in,
                              void* d_out, int out_size)
{
    const float* x    = (const float*)d_in[0];
    const float* Wqkv = (const float*)d_in[1];
    const float* Wout = (const float*)d_in[2];
    const unsigned char* mask = (const unsigned char*)d_in[3];
    float* out = (float*)d_out;

    __half *xh, *wqh, *woh, *qvh, *qvl, *cth;
    uint8_t *x8, *wq8, *wo8, *ct8;
    cudaGetSymbolAddress((void**)&xh,  g_xh);
    cudaGetSymbolAddress((void**)&x8,  g_x8);
    cudaGetSymbolAddress((void**)&wqh, g_wqkvh);
    cudaGetSymbolAddress((void**)&wq8, g_wqkv8);
    cudaGetSymbolAddress((void**)&woh, g_wouth);
    cudaGetSymbolAddress((void**)&wo8, g_wout8);
    cudaGetSymbolAddress((void**)&qvh, g_qkvh);
    cudaGetSymbolAddress((void**)&qvl, g_qkvl);
    cudaGetSymbolAddress((void**)&cth, g_cth);
    cudaGetSymbolAddress((void**)&ct8, g_ct8);

    const int gemm_smem = 2 * GSTAGE_B;     // 81920
    const int flash_smem = FSMEM_TOTAL;
    static int attrs_set = 0;
    if (!attrs_set) {
        cudaFuncSetAttribute(gemm_mma, cudaFuncAttributeMaxDynamicSharedMemorySize, gemm_smem);
        cudaFuncSetAttribute(flash_mma, cudaFuncAttributeMaxDynamicSharedMemorySize, flash_smem);
        attrs_set = 1;
    }

    // 0) splits: x (scale 1), weights (scale 16)
    {
        int n4x = (B_ * S_ * D_) / 4;
        split_pack<<<(n4x + 255) / 256, 256>>>(x, xh, x8, 1.0f, D_, n4x);
        int n4w = (3 * D_ * D_) / 4;
        split_pack<<<(n4w + 255) / 256, 256>>>(Wqkv, wqh, wq8, 16.0f, D_, n4w);
        int n4o = (D_ * D_) / 4;
        split_pack<<<(n4o + 255) / 256, 256>>>(Wout, woh, wo8, 16.0f, D_, n4o);
    }

    // 1) qkv = x @ Wqkv^T -> fp16 hi/lo
    {
        dim3 grid((3 * D_) / 128, (B_ * S_) / 128);
        gemm_mma<<<grid, 256, gemm_smem>>>(xh, x8, wqh, wq8, nullptr, qvh, qvl, 3 * D_, D_, 1);
    }
    // 2) flash attention -> ctx fp16 hi + fp8 pack
    {
        dim3 grid(S_ / 64, B_ * H_);
        flash_mma<<<grid, 128, flash_smem>>>(qvh, qvl, mask, cth, ct8);
    }
    // 3) out = ctx @ Wout^T -> f32
    {
        dim3 grid(D_ / 128, (B_ * S_) / 128);
        gemm_mma<<<grid, 256, gemm_smem>>>(cth, ct8, woh, wo8, out, nullptr, nullptr, D_, D_, 0);
    }
}

// round 11
// speedup vs baseline: 1.5968x; 1.5968x over previous
#include <cuda_runtime.h>
#include <cuda_fp16.h>
#include <math.h>
#include <stdint.h>

#define B_  2
#define S_  2048
#define D_  1024
#define H_  16
#define DK_ 64
#define SCALE_ 0.125f
#define LOG2E_ 1.44269504f
#define TNEG_ (-86562.0f)   // -60000 * log2(e)
#define LOSC_ 512.0f
#define LOSCI_ (1.0f / 512.0f)

// ---------------- scratch ----------------
__device__ __half g_xh[B_ * S_ * D_];
__device__ __half g_xl[B_ * S_ * D_];          // x lo * 512
__device__ __half g_wqh[3 * D_ * D_];
__device__ __half g_wql[3 * D_ * D_];          // Wqkv lo * 512
__device__ __half g_woh[D_ * D_];
__device__ __half g_wol[D_ * D_];              // unused (1-term out), kept for split kernel symmetry
__device__ __half g_qkvh[B_ * S_ * 3 * D_];
__device__ __half g_qkvl[B_ * S_ * 3 * D_];    // q,k lo unscaled; V region unwritten/unused
__device__ __half g_cth[B_ * S_ * D_];

// ================= helpers =================
__device__ __forceinline__ uint32_t smem_u32(const void* p) {
    uint32_t a;
    asm("{ .reg .u64 t; cvta.to.shared.u64 t, %1; cvt.u32.u64 %0, t; }" : "=r"(a) : "l"(p));
    return a;
}
#define CP16(dst, src) asm volatile("cp.async.cg.shared.global [%0], [%1], 16;" :: "r"(dst), "l"(src) : "memory")
#define CP_COMMIT()    asm volatile("cp.async.commit_group;" ::: "memory")
#define CP_WAIT0()     asm volatile("cp.async.wait_group 0;" ::: "memory")

__device__ __forceinline__ void ldsm4(uint32_t* r, uint32_t addr) {
    asm volatile("ldmatrix.sync.aligned.m8n8.x4.shared.b16 {%0,%1,%2,%3}, [%4];"
        : "=r"(r[0]), "=r"(r[1]), "=r"(r[2]), "=r"(r[3]) : "r"(addr));
}
__device__ __forceinline__ void ldsm4t(uint32_t* r, uint32_t addr) {
    asm volatile("ldmatrix.sync.aligned.m8n8.x4.trans.shared.b16 {%0,%1,%2,%3}, [%4];"
        : "=r"(r[0]), "=r"(r[1]), "=r"(r[2]), "=r"(r[3]) : "r"(addr));
}
__device__ __forceinline__ void mma16816(float* d, const uint32_t* a, const uint32_t* b) {
    asm volatile("mma.sync.aligned.m16n8k16.row.col.f32.f16.f16.f32 "
        "{%0,%1,%2,%3}, {%4,%5,%6,%7}, {%8,%9}, {%0,%1,%2,%3};"
        : "+f"(d[0]), "+f"(d[1]), "+f"(d[2]), "+f"(d[3])
        : "r"(a[0]), "r"(a[1]), "r"(a[2]), "r"(a[3]), "r"(b[0]), "r"(b[1]));
}
__device__ __forceinline__ float ex2(float x) {
    float y; asm("ex2.approx.ftz.f32 %0, %1;" : "=f"(y) : "f"(x)); return y;
}
__device__ __forceinline__ uint32_t packh2(float a, float b) {
    __half ha = __float2half_rn(a), hb = __float2half_rn(b);
    return (uint32_t)__half_as_ushort(ha) | ((uint32_t)__half_as_ushort(hb) << 16);
}
// fp16 hi + UNSCALED lo
__device__ __forceinline__ void split2h(float a, float b, uint32_t& hi, uint32_t& lo) {
    __half ha = __float2half_rn(a), hb = __float2half_rn(b);
    hi = (uint32_t)__half_as_ushort(ha) | ((uint32_t)__half_as_ushort(hb) << 16);
    lo = packh2(a - __half2float(ha), b - __half2float(hb));
}

// ================= split fp32 -> fp16 hi + lo*losc =================
__global__ void split_pair(const float* __restrict__ in, __half* __restrict__ hi,
                           __half* __restrict__ lo, float losc, int n4) {
    int i = blockIdx.x * blockDim.x + threadIdx.x;
    if (i >= n4) return;
    float4 v = ((const float4*)in)[i];
    float f[4] = {v.x, v.y, v.z, v.w};
    __half h[4];
    uint32_t hw[2], lw[2];
    #pragma unroll
    for (int j = 0; j < 4; j++) h[j] = __float2half_rn(f[j]);
    hw[0] = (uint32_t)__half_as_ushort(h[0]) | ((uint32_t)__half_as_ushort(h[1]) << 16);
    hw[1] = (uint32_t)__half_as_ushort(h[2]) | ((uint32_t)__half_as_ushort(h[3]) << 16);
    lw[0] = packh2((f[0] - __half2float(h[0])) * losc, (f[1] - __half2float(h[1])) * losc);
    lw[1] = packh2((f[2] - __half2float(h[2])) * losc, (f[3] - __half2float(h[3])) * losc);
    ((uint2*)hi)[i] = make_uint2(hw[0], hw[1]);
    ((uint2*)lo)[i] = make_uint2(lw[0], lw[1]);
}

// ================= 3-term GEMM (hi*hi -> acc; cross(x512) -> acc2) =================
// 128x128 tile, BK=32, 256 threads, 2-stage. Writes fp16 hi + unscaled lo.
#define GSTRIDE_B 80
#define GTILE_B (128 * GSTRIDE_B)       // 10240
#define G3STAGE_B (4 * GTILE_B)         // Ah, Al, Bh, Bl

__global__ __launch_bounds__(256)
void gemm3(const __half* __restrict__ Ah, const __half* __restrict__ Al,
           const __half* __restrict__ Bh, const __half* __restrict__ Bl,
           __half* __restrict__ Ch, __half* __restrict__ Cl, int ldc, int K)
{
    extern __shared__ char sm[];
    const int tid = threadIdx.x, wid = tid >> 5, lane = tid & 31;
    const int wm = wid & 3, wn = wid >> 2;
    uint32_t sbase = smem_u32(sm);

    const char* gt[4];
    gt[0] = (const char*)(Ah + (size_t)blockIdx.y * 128 * K);
    gt[1] = (const char*)(Al + (size_t)blockIdx.y * 128 * K);
    gt[2] = (const char*)(Bh + (size_t)blockIdx.x * 128 * K);
    gt[3] = (const char*)(Bl + (size_t)blockIdx.x * 128 * K);

    float acc[2][8][4] = {};
    float acc2[2][8][4] = {};

    const int lrow = tid >> 2, lcol = tid & 3;
    auto load_stage = [&](int j) {
        uint32_t sb = sbase + (j & 1) * G3STAGE_B;
        const size_t gc = (size_t)j * 64;
        #pragma unroll
        for (int t = 0; t < 4; t++) {
            const char* g = gt[t] + gc;
            uint32_t tb = sb + t * GTILE_B;
            #pragma unroll
            for (int i = 0; i < 2; i++) {
                int row = lrow + i * 64;
                CP16(tb + row * GSTRIDE_B + lcol * 16,
                     g + (size_t)row * K * 2 + lcol * 16);
            }
        }
    };

    load_stage(0); CP_COMMIT();
    const int NK = K / 32;

    const uint32_t arow = (lane & 15), acs = (lane >> 4) * 16;
    const uint32_t brow = (lane & 7) + (lane >> 4) * 8, bcs = ((lane >> 3) & 1) * 16;

    for (int j = 0; j < NK; j++) {
        CP_WAIT0();
        __syncthreads();
        if (j + 1 < NK) { load_stage(j + 1); CP_COMMIT(); }

        uint32_t sb = sbase + (j & 1) * G3STAGE_B;
        uint32_t aH = sb + wm * 32 * GSTRIDE_B;
        uint32_t aL = aH + GTILE_B;
        uint32_t bH = sb + 2 * GTILE_B + wn * 64 * GSTRIDE_B;
        uint32_t bL = bH + GTILE_B;

        #pragma unroll
        for (int ks = 0; ks < 2; ks++) {
            uint32_t ah[2][4], al[2][4];
            #pragma unroll
            for (int mt = 0; mt < 2; mt++) {
                ldsm4(ah[mt], aH + (mt * 16 + arow) * GSTRIDE_B + ks * 32 + acs);
                ldsm4(al[mt], aL + (mt * 16 + arow) * GSTRIDE_B + ks * 32 + acs);
            }
            #pragma unroll
            for (int np = 0; np < 4; np++) {
                uint32_t bh[4], bl[4];
                ldsm4(bh, bH + (np * 16 + brow) * GSTRIDE_B + ks * 32 + bcs);
                ldsm4(bl, bL + (np * 16 + brow) * GSTRIDE_B + ks * 32 + bcs);
                #pragma unroll
                for (int mt = 0; mt < 2; mt++) {
                    mma16816(acc[mt][2 * np],      ah[mt], &bh[0]);
                    mma16816(acc[mt][2 * np + 1],  ah[mt], &bh[2]);
                    mma16816(acc2[mt][2 * np],     ah[mt], &bl[0]);
                    mma16816(acc2[mt][2 * np + 1], ah[mt], &bl[2]);
                    mma16816(acc2[mt][2 * np],     al[mt], &bh[0]);
                    mma16816(acc2[mt][2 * np + 1], al[mt], &bh[2]);
                }
            }
        }
    }

    const int rb = blockIdx.y * 128 + wm * 32 + (lane >> 2);
    const int cb = blockIdx.x * 128 + wn * 64 + (lane & 3) * 2;
    #pragma unroll
    for (int mt = 0; mt < 2; mt++)
        #pragma unroll
        for (int half = 0; half < 2; half++) {
            int r = rb + mt * 16 + half * 8;
            #pragma unroll
            for (int nt = 0; nt < 8; nt++) {
                int c = cb + nt * 8;
                float v0 = acc[mt][nt][half * 2 + 0] + acc2[mt][nt][half * 2 + 0] * LOSCI_;
                float v1 = acc[mt][nt][half * 2 + 1] + acc2[mt][nt][half * 2 + 1] * LOSCI_;
                uint32_t hi, lo;
                split2h(v0, v1, hi, lo);
                *(uint32_t*)(Ch + (size_t)r * ldc + c) = hi;
                *(uint32_t*)(Cl + (size_t)r * ldc + c) = lo;
            }
        }
}

// ================= 1-term fp16 GEMM =================
#define G1STAGE_B (2 * GTILE_B)         // Ah, Bh

__global__ __launch_bounds__(256)
void gemm1(const __half* __restrict__ Ah, const __half* __restrict__ Bh,
           float* __restrict__ Cf, __half* __restrict__ Ch, int ldc, int K, int fp16out)
{
    extern __shared__ char sm[];
    const int tid = threadIdx.x, wid = tid >> 5, lane = tid & 31;
    const int wm = wid & 3, wn = wid >> 2;
    uint32_t sbase = smem_u32(sm);

    const char* gA = (const char*)(Ah + (size_t)blockIdx.y * 128 * K);
    const char* gB = (const char*)(Bh + (size_t)blockIdx.x * 128 * K);

    float acc[2][8][4] = {};

    const int lrow = tid >> 2, lcol = tid & 3;
    auto load_stage = [&](int j) {
        uint32_t sb = sbase + (j & 1) * G1STAGE_B;
        const size_t gc = (size_t)j * 64;
        #pragma unroll
        for (int i = 0; i < 2; i++) {
            int row = lrow + i * 64;
            uint32_t so = row * GSTRIDE_B + lcol * 16;
            size_t go = gc + (size_t)row * K * 2 + lcol * 16;
            CP16(sb + so, gA + go);
            CP16(sb + GTILE_B + so, gB + go);
        }
    };

    load_stage(0); CP_COMMIT();
    const int NK = K / 32;

    const uint32_t arow = (lane & 15), acs = (lane >> 4) * 16;
    const uint32_t brow = (lane & 7) + (lane >> 4) * 8, bcs = ((lane >> 3) & 1) * 16;

    for (int j = 0; j < NK; j++) {
        CP_WAIT0();
        __syncthreads();
        if (j + 1 < NK) { load_stage(j + 1); CP_COMMIT(); }

        uint32_t sb = sbase + (j & 1) * G1STAGE_B;
        uint32_t aH = sb + wm * 32 * GSTRIDE_B;
        uint32_t bH = sb + GTILE_B + wn * 64 * GSTRIDE_B;

        #pragma unroll
        for (int ks = 0; ks < 2; ks++) {
            uint32_t ah[2][4];
            #pragma unroll
            for (int mt = 0; mt < 2; mt++)
                ldsm4(ah[mt], aH + (mt * 16 + arow) * GSTRIDE_B + ks * 32 + acs);
            #pragma unroll
            for (int np = 0; np < 4; np++) {
                uint32_t bh[4];
                ldsm4(bh, bH + (np * 16 + brow) * GSTRIDE_B + ks * 32 + bcs);
                #pragma unroll
                for (int mt = 0; mt < 2; mt++) {
                    mma16816(acc[mt][2 * np],     ah[mt], &bh[0]);
                    mma16816(acc[mt][2 * np + 1], ah[mt], &bh[2]);
                }
            }
        }
    }

    const int rb = blockIdx.y * 128 + wm * 32 + (lane >> 2);
    const int cb = blockIdx.x * 128 + wn * 64 + (lane & 3) * 2;
    #pragma unroll
    for (int mt = 0; mt < 2; mt++)
        #pragma unroll
        for (int half = 0; half < 2; half++) {
            int r = rb + mt * 16 + half * 8;
            #pragma unroll
            for (int nt = 0; nt < 8; nt++) {
                int c = cb + nt * 8;
                float v0 = acc[mt][nt][half * 2 + 0];
                float v1 = acc[mt][nt][half * 2 + 1];
                if (fp16out)
                    *(uint32_t*)(Ch + (size_t)r * ldc + c) = packh2(v0, v1);
                else
                    *(float2*)(Cf + (size_t)r * ldc + c) = make_float2(v0, v1);
            }
        }
}

// ================= flash attention: S 3-term, PV 1-term =================
#define FSTRIDE_B 144
#define FTILE_B (64 * FSTRIDE_B)        // 9216
#define FSTAGE_B (3 * FTILE_B)          // Kh, Kl, Vh
#define FQ_OFF 0
#define FST_OFF (2 * FTILE_B)
#define FMS_OFF (FST_OFF + 2 * FSTAGE_B)
#define FSMEM_TOTAL (FMS_OFF + 128)

__global__ __launch_bounds__(128, 2)
void flash_mma(const __half* __restrict__ qh, const __half* __restrict__ ql,
               const unsigned char* __restrict__ mask, __half* __restrict__ cth)
{
    extern __shared__ char sm[];
    const int tid = threadIdx.x, wid = tid >> 5, lane = tid & 31;
    const int bh_ = blockIdx.y, b = bh_ >> 4, h = bh_ & 15;
    const int q0 = blockIdx.x * 64;
    uint32_t sbase = smem_u32(sm);
    const uint32_t QH = sbase + FQ_OFF, QL = QH + FTILE_B;
    const uint32_t STG = sbase + FST_OFF;

    const size_t rs = 3 * D_;
    const char* qbh = (const char*)(qh + ((size_t)b * S_ + q0) * rs + h * 64);
    const char* qbl = (const char*)(ql + ((size_t)b * S_ + q0) * rs + h * 64);
    const char* kbh = (const char*)(qh + (size_t)b * S_ * rs + D_ + h * 64);
    const char* kbl = (const char*)(ql + (size_t)b * S_ * rs + D_ + h * 64);
    const char* vbh = (const char*)(qh + (size_t)b * S_ * rs + 2 * D_ + h * 64);

    auto load_kv = [&](int j) {
        uint32_t sb = STG + (j & 1) * FSTAGE_B;
        size_t gk = (size_t)j * 64 * rs * 2;
        #pragma unroll
        for (int i = 0; i < 4; i++) {
            int c = tid + i * 128;
            int row = c >> 3, col = c & 7;
            size_t go = gk + (size_t)row * rs * 2 + col * 16;
            uint32_t so = row * FSTRIDE_B + col * 16;
            CP16(sb + 0 * FTILE_B + so, kbh + go);
            CP16(sb + 1 * FTILE_B + so, kbl + go);
            CP16(sb + 2 * FTILE_B + so, vbh + go);
        }
    };
    auto store_mask = [&](int j) {
        if (tid < 16) {
            uint32_t v = *(const uint32_t*)(mask + (size_t)b * S_ + j * 64 + tid * 4);
            *(uint32_t*)(sm + FMS_OFF + (j & 1) * 64 + tid * 4) = v;
        }
    };

    #pragma unroll
    for (int i = 0; i < 4; i++) {
        int c = tid + i * 128;
        int row = c >> 3, col = c & 7;
        uint32_t so = row * FSTRIDE_B + col * 16;
        CP16(QH + so, qbh + (size_t)row * rs * 2 + col * 16);
        CP16(QL + so, qbl + (size_t)row * rs * 2 + col * 16);
    }
    load_kv(0); CP_COMMIT();
    store_mask(0);

    uint32_t qfh[4][4], qfl[4][4];
    float o[8][4] = {};
    float m0 = -1e30f, m1 = -1e30f, l0 = 0.0f, l1 = 0.0f;

    const uint32_t arow = (lane & 15), acs = (lane >> 4) * 16;
    const uint32_t brow = (lane & 7) + (lane >> 4) * 8, bcs = ((lane >> 3) & 1) * 16;

    for (int kt = 0; kt < S_ / 64; kt++) {
        CP_WAIT0();
        __syncthreads();
        if (kt == 0) {
            #pragma unroll
            for (int ks = 0; ks < 4; ks++) {
                ldsm4(qfh[ks], QH + (wid * 16 + arow) * FSTRIDE_B + ks * 32 + acs);
                ldsm4(qfl[ks], QL + (wid * 16 + arow) * FSTRIDE_B + ks * 32 + acs);
            }
        }
        if (kt + 1 < S_ / 64) { load_kv(kt + 1); CP_COMMIT(); store_mask(kt + 1); }

        uint32_t sb = STG + (kt & 1) * FSTAGE_B;
        uint32_t KH = sb, KL = sb + FTILE_B, VH = sb + 2 * FTILE_B;

        // ---- S = Q K^T, 3-term (fp32 accum, unscaled lo — proven path) ----
        float s[8][4] = {};
        #pragma unroll
        for (int ks = 0; ks < 4; ks++) {
            uint32_t kh[4][4], kl[4][4];
            #pragma unroll
            for (int np = 0; np < 4; np++) {
                ldsm4(kh[np], KH + (np * 16 + brow) * FSTRIDE_B + ks * 32 + bcs);
                ldsm4(kl[np], KL + (np * 16 + brow) * FSTRIDE_B + ks * 32 + bcs);
            }
            #pragma unroll
            for (int np = 0; np < 4; np++) {
                mma16816(s[2 * np],     qfh[ks], &kh[np][0]);
                mma16816(s[2 * np + 1], qfh[ks], &kh[np][2]);
                mma16816(s[2 * np],     qfh[ks], &kl[np][0]);
                mma16816(s[2 * np + 1], qfh[ks], &kl[np][2]);
                mma16816(s[2 * np],     qfl[ks], &kh[np][0]);
                mma16816(s[2 * np + 1], qfl[ks], &kh[np][2]);
            }
        }

        // ---- softmax (exp2 domain) ----
        const float CM = SCALE_ * LOG2E_;
        float rmax0 = -1e30f, rmax1 = -1e30f;
        #pragma unroll
        for (int nt = 0; nt < 8; nt++) {
            unsigned short mm = *(const unsigned short*)(sm + FMS_OFF + (kt & 1) * 64 + nt * 8 + (lane & 3) * 2);
            bool k0m = (mm & 0xFF) != 0, k1m = (mm >> 8) != 0;
            s[nt][0] = k0m ? TNEG_ : s[nt][0] * CM;
            s[nt][1] = k1m ? TNEG_ : s[nt][1] * CM;
            s[nt][2] = k0m ? TNEG_ : s[nt][2] * CM;
            s[nt][3] = k1m ? TNEG_ : s[nt][3] * CM;
            rmax0 = fmaxf(rmax0, fmaxf(s[nt][0], s[nt][1]));
            rmax1 = fmaxf(rmax1, fmaxf(s[nt][2], s[nt][3]));
        }
        rmax0 = fmaxf(rmax0, __shfl_xor_sync(0xffffffffu, rmax0, 1));
        rmax0 = fmaxf(rmax0, __shfl_xor_sync(0xffffffffu, rmax0, 2));
        rmax1 = fmaxf(rmax1, __shfl_xor_sync(0xffffffffu, rmax1, 1));
        rmax1 = fmaxf(rmax1, __shfl_xor_sync(0xffffffffu, rmax1, 2));
        float mn0 = fmaxf(m0, rmax0), mn1 = fmaxf(m1, rmax1);
        float cr0 = ex2(m0 - mn0), cr1 = ex2(m1 - mn1);
        m0 = mn0; m1 = mn1;
        float ps0 = 0.0f, ps1 = 0.0f;
        #pragma unroll
        for (int nt = 0; nt < 8; nt++) {
            s[nt][0] = ex2(s[nt][0] - mn0);
            s[nt][1] = ex2(s[nt][1] - mn0);
            s[nt][2] = ex2(s[nt][2] - mn1);
            s[nt][3] = ex2(s[nt][3] - mn1);
            ps0 += s[nt][0] + s[nt][1];
            ps1 += s[nt][2] + s[nt][3];
        }
        ps0 += __shfl_xor_sync(0xffffffffu, ps0, 1);
        ps0 += __shfl_xor_sync(0xffffffffu, ps0, 2);
        ps1 += __shfl_xor_sync(0xffffffffu, ps1, 1);
        ps1 += __shfl_xor_sync(0xffffffffu, ps1, 2);
        l0 = l0 * cr0 + ps0;
        l1 = l1 * cr1 + ps1;
        #pragma unroll
        for (int nt = 0; nt < 8; nt++) {
            o[nt][0] *= cr0; o[nt][1] *= cr0;
            o[nt][2] *= cr1; o[nt][3] *= cr1;
        }

        // P -> single fp16 fragments
        uint32_t ph[4][4];
        #pragma unroll
        for (int kp = 0; kp < 4; kp++) {
            ph[kp][0] = packh2(s[2 * kp][0],     s[2 * kp][1]);
            ph[kp][1] = packh2(s[2 * kp][2],     s[2 * kp][3]);
            ph[kp][2] = packh2(s[2 * kp + 1][0], s[2 * kp + 1][1]);
            ph[kp][3] = packh2(s[2 * kp + 1][2], s[2 * kp + 1][3]);
        }

        // ---- O += P V, 1-term ----
        #pragma unroll
        for (int kp = 0; kp < 4; kp++) {
            uint32_t vh[4][4];
            uint32_t krow = kp * 16 + (lane & 15);
            uint32_t dbyte = (lane >> 4) * 16;
            #pragma unroll
            for (int dp = 0; dp < 4; dp++)
                ldsm4t(vh[dp], VH + krow * FSTRIDE_B + dp * 32 + dbyte);
            #pragma unroll
            for (int dp = 0; dp < 4; dp++) {
                mma16816(o[2 * dp],     ph[kp], &vh[dp][0]);
                mma16816(o[2 * dp + 1], ph[kp], &vh[dp][2]);
            }
        }
    }

    // epilogue: ctx -> fp16
    float il0 = 1.0f / l0, il1 = 1.0f / l1;
    int r0 = q0 + wid * 16 + (lane >> 2);
    int cbase = h * 64 + (lane & 3) * 2;
    #pragma unroll
    for (int nt = 0; nt < 8; nt++) {
        int c = cbase + nt * 8;
        size_t i0 = ((size_t)b * S_ + r0) * D_ + c;
        *(uint32_t*)(cth + i0) = packh2(o[nt][0] * il0, o[nt][1] * il0);
        size_t i1 = i0 + 8 * D_;
        *(uint32_t*)(cth + i1) = packh2(o[nt][2] * il1, o[nt][3] * il1);
    }
}

// ---------------- launch ----------------
extern "C" void kernel_launch(void* const* d_in, const int* in_sizes, int n_in,
                              void* d_out, int out_size)
{
    const float* x    = (const float*)d_in[0];
    const float* Wqkv = (const float*)d_in[1];
    const float* Wout = (const float*)d_in[2];
    const unsigned char* mask = (const unsigned char*)d_in[3];
    float* out = (float*)d_out;

    __half *xh, *xl, *wqh, *wql, *woh, *wol, *qvh, *qvl, *cth;
    cudaGetSymbolAddress((void**)&xh,  g_xh);
    cudaGetSymbolAddress((void**)&xl,  g_xl);
    cudaGetSymbolAddress((void**)&wqh, g_wqh);
    cudaGetSymbolAddress((void**)&wql, g_wql);
    cudaGetSymbolAddress((void**)&woh, g_woh);
    cudaGetSymbolAddress((void**)&wol, g_wol);
    cudaGetSymbolAddress((void**)&qvh, g_qkvh);
    cudaGetSymbolAddress((void**)&qvl, g_qkvl);
    cudaGetSymbolAddress((void**)&cth, g_cth);

    const int g3_smem = 2 * G3STAGE_B;   // 81920
    const int g1_smem = 2 * G1STAGE_B;   // 40960
    const int flash_smem = FSMEM_TOTAL;  // 73856
    static int attrs_set = 0;
    if (!attrs_set) {
        cudaFuncSetAttribute(gemm3, cudaFuncAttributeMaxDynamicSharedMemorySize, g3_smem);
        cudaFuncSetAttribute(gemm1, cudaFuncAttributeMaxDynamicSharedMemorySize, g1_smem);
        cudaFuncSetAttribute(flash_mma, cudaFuncAttributeMaxDynamicSharedMemorySize, flash_smem);
        attrs_set = 1;
    }

    // 0) splits
    {
        int n4x = (B_ * S_ * D_) / 4;
        split_pair<<<(n4x + 255) / 256, 256>>>(x, xh, xl, LOSC_, n4x);
        int n4w = (3 * D_ * D_) / 4;
        split_pair<<<(n4w + 255) / 256, 256>>>(Wqkv, wqh, wql, LOSC_, n4w);
        int n4o = (D_ * D_) / 4;
        split_pair<<<(n4o + 255) / 256, 256>>>(Wout, woh, wol, LOSC_, n4o);
    }

    // 1a) Q,K = x @ Wqkv[0:2D]^T  (3-term) -> qkv hi/lo cols [0,2D)
    {
        dim3 grid((2 * D_) / 128, (B_ * S_) / 128);
        gemm3<<<grid, 256, g3_smem>>>(xh, xl, wqh, wql, qvh, qvl, 3 * D_, D_);
    }
    // 1b) V = x @ Wqkv[2D:3D]^T  (1-term) -> qkv hi cols [2D,3D)
    {
        dim3 grid(D_ / 128, (B_ * S_) / 128);
        gemm1<<<grid, 256, g1_smem>>>(xh, wqh + (size_t)2 * D_ * D_,
                                      nullptr, qvh + 2 * D_, 3 * D_, D_, 1);
    }
    // 2) flash attention -> ctx fp16
    {
        dim3 grid(S_ / 64, B_ * H_);
        flash_mma<<<grid, 128, flash_smem>>>(qvh, qvl, mask, cth);
    }
    // 3) out = ctx @ Wout^T (1-term) -> f32
    {
        dim3 grid(D_ / 128, (B_ * S_) / 128);
        gemm1<<<grid, 256, g1_smem>>>(cth, woh, out, nullptr, D_, D_, 0);
    }
}

// round 12
// speedup vs baseline: 1.6797x; 1.0519x over previous
#include <cuda_runtime.h>
#include <cuda_fp16.h>
#include <math.h>
#include <stdint.h>

#define B_  2
#define S_  2048
#define D_  1024
#define H_  16
#define DK_ 64
#define SCALE_ 0.125f
#define LOG2E_ 1.44269504f
#define TNEG_ (-86562.0f)   // -60000 * log2(e)

// ---------------- scratch ----------------
__device__ __half g_xh[B_ * S_ * D_];
__device__ __half g_xl[B_ * S_ * D_];          // unscaled residual
__device__ __half g_wqh[3 * D_ * D_];
__device__ __half g_wql[3 * D_ * D_];          // unscaled residual
__device__ __half g_woh[D_ * D_];
__device__ __half g_qkvh[B_ * S_ * 3 * D_];
__device__ __half g_qkvl[B_ * S_ * 3 * D_];    // q,k lo unscaled; V region unused
__device__ __half g_cth[B_ * S_ * D_];

// ================= helpers =================
__device__ __forceinline__ uint32_t smem_u32(const void* p) {
    uint32_t a;
    asm("{ .reg .u64 t; cvta.to.shared.u64 t, %1; cvt.u32.u64 %0, t; }" : "=r"(a) : "l"(p));
    return a;
}
#define CP16(dst, src) asm volatile("cp.async.cg.shared.global [%0], [%1], 16;" :: "r"(dst), "l"(src) : "memory")
#define CP_COMMIT()    asm volatile("cp.async.commit_group;" ::: "memory")
#define CP_WAIT0()     asm volatile("cp.async.wait_group 0;" ::: "memory")

__device__ __forceinline__ void ldsm4(uint32_t* r, uint32_t addr) {
    asm volatile("ldmatrix.sync.aligned.m8n8.x4.shared.b16 {%0,%1,%2,%3}, [%4];"
        : "=r"(r[0]), "=r"(r[1]), "=r"(r[2]), "=r"(r[3]) : "r"(addr));
}
__device__ __forceinline__ void ldsm4t(uint32_t* r, uint32_t addr) {
    asm volatile("ldmatrix.sync.aligned.m8n8.x4.trans.shared.b16 {%0,%1,%2,%3}, [%4];"
        : "=r"(r[0]), "=r"(r[1]), "=r"(r[2]), "=r"(r[3]) : "r"(addr));
}
__device__ __forceinline__ void mma16816(float* d, const uint32_t* a, const uint32_t* b) {
    asm volatile("mma.sync.aligned.m16n8k16.row.col.f32.f16.f16.f32 "
        "{%0,%1,%2,%3}, {%4,%5,%6,%7}, {%8,%9}, {%0,%1,%2,%3};"
        : "+f"(d[0]), "+f"(d[1]), "+f"(d[2]), "+f"(d[3])
        : "r"(a[0]), "r"(a[1]), "r"(a[2]), "r"(a[3]), "r"(b[0]), "r"(b[1]));
}
__device__ __forceinline__ float ex2(float x) {
    float y; asm("ex2.approx.ftz.f32 %0, %1;" : "=f"(y) : "f"(x)); return y;
}
__device__ __forceinline__ uint32_t packh2(float a, float b) {
    __half ha = __float2half_rn(a), hb = __float2half_rn(b);
    return (uint32_t)__half_as_ushort(ha) | ((uint32_t)__half_as_ushort(hb) << 16);
}
__device__ __forceinline__ void split2h(float a, float b, uint32_t& hi, uint32_t& lo) {
    __half ha = __float2half_rn(a), hb = __float2half_rn(b);
    hi = (uint32_t)__half_as_ushort(ha) | ((uint32_t)__half_as_ushort(hb) << 16);
    lo = packh2(a - __half2float(ha), b - __half2float(hb));
}

// ================= split fp32 -> fp16 hi + unscaled lo =================
__global__ void split_pair(const float* __restrict__ in, __half* __restrict__ hi,
                           __half* __restrict__ lo, int n4) {
    int i = blockIdx.x * blockDim.x + threadIdx.x;
    if (i >= n4) return;
    float4 v = ((const float4*)in)[i];
    uint32_t h0, l0, h1, l1;
    split2h(v.x, v.y, h0, l0);
    split2h(v.z, v.w, h1, l1);
    ((uint2*)hi)[i] = make_uint2(h0, h1);
    ((uint2*)lo)[i] = make_uint2(l0, l1);
}
__global__ void split_hi(const float* __restrict__ in, __half* __restrict__ hi, int n4) {
    int i = blockIdx.x * blockDim.x + threadIdx.x;
    if (i >= n4) return;
    float4 v = ((const float4*)in)[i];
    ((uint2*)hi)[i] = make_uint2(packh2(v.x, v.y), packh2(v.z, v.w));
}

// ================= 3-term GEMM, single fp32 accumulator =================
// 128x128 tile, BK=32, 256 threads, 2-stage, 2 CTAs/SM (R5-proven shape).
#define GSTRIDE_B 80
#define GTILE_B (128 * GSTRIDE_B)       // 10240
#define G3STAGE_B (4 * GTILE_B)         // Ah, Al, Bh, Bl

__global__ __launch_bounds__(256, 2)
void gemm3(const __half* __restrict__ Ah, const __half* __restrict__ Al,
           const __half* __restrict__ Bh, const __half* __restrict__ Bl,
           __half* __restrict__ Ch, __half* __restrict__ Cl, int ldc, int K)
{
    extern __shared__ char sm[];
    const int tid = threadIdx.x, wid = tid >> 5, lane = tid & 31;
    const int wm = wid & 3, wn = wid >> 2;
    uint32_t sbase = smem_u32(sm);

    const char* gt[4];
    gt[0] = (const char*)(Ah + (size_t)blockIdx.y * 128 * K);
    gt[1] = (const char*)(Al + (size_t)blockIdx.y * 128 * K);
    gt[2] = (const char*)(Bh + (size_t)blockIdx.x * 128 * K);
    gt[3] = (const char*)(Bl + (size_t)blockIdx.x * 128 * K);

    float acc[2][8][4] = {};

    const int lrow = tid >> 2, lcol = tid & 3;
    auto load_stage = [&](int j) {
        uint32_t sb = sbase + (j & 1) * G3STAGE_B;
        const size_t gc = (size_t)j * 64;
        #pragma unroll
        for (int t = 0; t < 4; t++) {
            const char* g = gt[t] + gc;
            uint32_t tb = sb + t * GTILE_B;
            #pragma unroll
            for (int i = 0; i < 2; i++) {
                int row = lrow + i * 64;
                CP16(tb + row * GSTRIDE_B + lcol * 16,
                     g + (size_t)row * K * 2 + lcol * 16);
            }
        }
    };

    load_stage(0); CP_COMMIT();
    const int NK = K / 32;

    const uint32_t arow = (lane & 15), acs = (lane >> 4) * 16;
    const uint32_t brow = (lane & 7) + (lane >> 4) * 8, bcs = ((lane >> 3) & 1) * 16;

    for (int j = 0; j < NK; j++) {
        CP_WAIT0();
        __syncthreads();
        if (j + 1 < NK) { load_stage(j + 1); CP_COMMIT(); }

        uint32_t sb = sbase + (j & 1) * G3STAGE_B;
        uint32_t aH = sb + wm * 32 * GSTRIDE_B;
        uint32_t aL = aH + GTILE_B;
        uint32_t bH = sb + 2 * GTILE_B + wn * 64 * GSTRIDE_B;
        uint32_t bL = bH + GTILE_B;

        #pragma unroll
        for (int ks = 0; ks < 2; ks++) {
            uint32_t ah[2][4], al[2][4];
            #pragma unroll
            for (int mt = 0; mt < 2; mt++) {
                ldsm4(ah[mt], aH + (mt * 16 + arow) * GSTRIDE_B + ks * 32 + acs);
                ldsm4(al[mt], aL + (mt * 16 + arow) * GSTRIDE_B + ks * 32 + acs);
            }
            #pragma unroll
            for (int np = 0; np < 4; np++) {
                uint32_t bh[4], bl[4];
                ldsm4(bh, bH + (np * 16 + brow) * GSTRIDE_B + ks * 32 + bcs);
                ldsm4(bl, bL + (np * 16 + brow) * GSTRIDE_B + ks * 32 + bcs);
                #pragma unroll
                for (int mt = 0; mt < 2; mt++) {
                    mma16816(acc[mt][2 * np],     ah[mt], &bh[0]);
                    mma16816(acc[mt][2 * np + 1], ah[mt], &bh[2]);
                    mma16816(acc[mt][2 * np],     ah[mt], &bl[0]);
                    mma16816(acc[mt][2 * np + 1], ah[mt], &bl[2]);
                    mma16816(acc[mt][2 * np],     al[mt], &bh[0]);
                    mma16816(acc[mt][2 * np + 1], al[mt], &bh[2]);
                }
            }
        }
    }

    const int rb = blockIdx.y * 128 + wm * 32 + (lane >> 2);
    const int cb = blockIdx.x * 128 + wn * 64 + (lane & 3) * 2;
    #pragma unroll
    for (int mt = 0; mt < 2; mt++)
        #pragma unroll
        for (int half = 0; half < 2; half++) {
            int r = rb + mt * 16 + half * 8;
            #pragma unroll
            for (int nt = 0; nt < 8; nt++) {
                int c = cb + nt * 8;
                uint32_t hi, lo;
                split2h(acc[mt][nt][half * 2 + 0], acc[mt][nt][half * 2 + 1], hi, lo);
                *(uint32_t*)(Ch + (size_t)r * ldc + c) = hi;
                *(uint32_t*)(Cl + (size_t)r * ldc + c) = lo;
            }
        }
}

// ================= 1-term fp16 GEMM =================
#define G1STAGE_B (2 * GTILE_B)

__global__ __launch_bounds__(256, 2)
void gemm1(const __half* __restrict__ Ah, const __half* __restrict__ Bh,
           float* __restrict__ Cf, __half* __restrict__ Ch, int ldc, int K, int fp16out)
{
    extern __shared__ char sm[];
    const int tid = threadIdx.x, wid = tid >> 5, lane = tid & 31;
    const int wm = wid & 3, wn = wid >> 2;
    uint32_t sbase = smem_u32(sm);

    const char* gA = (const char*)(Ah + (size_t)blockIdx.y * 128 * K);
    const char* gB = (const char*)(Bh + (size_t)blockIdx.x * 128 * K);

    float acc[2][8][4] = {};

    const int lrow = tid >> 2, lcol = tid & 3;
    auto load_stage = [&](int j) {
        uint32_t sb = sbase + (j & 1) * G1STAGE_B;
        const size_t gc = (size_t)j * 64;
        #pragma unroll
        for (int i = 0; i < 2; i++) {
            int row = lrow + i * 64;
            uint32_t so = row * GSTRIDE_B + lcol * 16;
            size_t go = gc + (size_t)row * K * 2 + lcol * 16;
            CP16(sb + so, gA + go);
            CP16(sb + GTILE_B + so, gB + go);
        }
    };

    load_stage(0); CP_COMMIT();
    const int NK = K / 32;

    const uint32_t arow = (lane & 15), acs = (lane >> 4) * 16;
    const uint32_t brow = (lane & 7) + (lane >> 4) * 8, bcs = ((lane >> 3) & 1) * 16;

    for (int j = 0; j < NK; j++) {
        CP_WAIT0();
        __syncthreads();
        if (j + 1 < NK) { load_stage(j + 1); CP_COMMIT(); }

        uint32_t sb = sbase + (j & 1) * G1STAGE_B;
        uint32_t aH = sb + wm * 32 * GSTRIDE_B;
        uint32_t bH = sb + GTILE_B + wn * 64 * GSTRIDE_B;

        #pragma unroll
        for (int ks = 0; ks < 2; ks++) {
            uint32_t ah[2][4];
            #pragma unroll
            for (int mt = 0; mt < 2; mt++)
                ldsm4(ah[mt], aH + (mt * 16 + arow) * GSTRIDE_B + ks * 32 + acs);
            #pragma unroll
            for (int np = 0; np < 4; np++) {
                uint32_t bh[4];
                ldsm4(bh, bH + (np * 16 + brow) * GSTRIDE_B + ks * 32 + bcs);
                #pragma unroll
                for (int mt = 0; mt < 2; mt++) {
                    mma16816(acc[mt][2 * np],     ah[mt], &bh[0]);
                    mma16816(acc[mt][2 * np + 1], ah[mt], &bh[2]);
                }
            }
        }
    }

    const int rb = blockIdx.y * 128 + wm * 32 + (lane >> 2);
    const int cb = blockIdx.x * 128 + wn * 64 + (lane & 3) * 2;
    #pragma unroll
    for (int mt = 0; mt < 2; mt++)
        #pragma unroll
        for (int half = 0; half < 2; half++) {
            int r = rb + mt * 16 + half * 8;
            #pragma unroll
            for (int nt = 0; nt < 8; nt++) {
                int c = cb + nt * 8;
                float v0 = acc[mt][nt][half * 2 + 0];
                float v1 = acc[mt][nt][half * 2 + 1];
                if (fp16out)
                    *(uint32_t*)(Ch + (size_t)r * ldc + c) = packh2(v0, v1);
                else
                    *(float2*)(Cf + (size_t)r * ldc + c) = make_float2(v0, v1);
            }
        }
}

// ================= flash attention: S 3-term, PV 1-term =================
#define FSTRIDE_B 144
#define FTILE_B (64 * FSTRIDE_B)
#define FSTAGE_B (3 * FTILE_B)          // Kh, Kl, Vh
#define FQ_OFF 0
#define FST_OFF (2 * FTILE_B)
#define FMS_OFF (FST_OFF + 2 * FSTAGE_B)
#define FSMEM_TOTAL (FMS_OFF + 128)

__global__ __launch_bounds__(128, 2)
void flash_mma(const __half* __restrict__ qh, const __half* __restrict__ ql,
               const unsigned char* __restrict__ mask, __half* __restrict__ cth)
{
    extern __shared__ char sm[];
    const int tid = threadIdx.x, wid = tid >> 5, lane = tid & 31;
    const int bh_ = blockIdx.y, b = bh_ >> 4, h = bh_ & 15;
    const int q0 = blockIdx.x * 64;
    uint32_t sbase = smem_u32(sm);
    const uint32_t QH = sbase + FQ_OFF, QL = QH + FTILE_B;
    const uint32_t STG = sbase + FST_OFF;

    const size_t rs = 3 * D_;
    const char* qbh = (const char*)(qh + ((size_t)b * S_ + q0) * rs + h * 64);
    const char* qbl = (const char*)(ql + ((size_t)b * S_ + q0) * rs + h * 64);
    const char* kbh = (const char*)(qh + (size_t)b * S_ * rs + D_ + h * 64);
    const char* kbl = (const char*)(ql + (size_t)b * S_ * rs + D_ + h * 64);
    const char* vbh = (const char*)(qh + (size_t)b * S_ * rs + 2 * D_ + h * 64);

    auto load_kv = [&](int j) {
        uint32_t sb = STG + (j & 1) * FSTAGE_B;
        size_t gk = (size_t)j * 64 * rs * 2;
        #pragma unroll
        for (int i = 0; i < 4; i++) {
            int c = tid + i * 128;
            int row = c >> 3, col = c & 7;
            size_t go = gk + (size_t)row * rs * 2 + col * 16;
            uint32_t so = row * FSTRIDE_B + col * 16;
            CP16(sb + 0 * FTILE_B + so, kbh + go);
            CP16(sb + 1 * FTILE_B + so, kbl + go);
            CP16(sb + 2 * FTILE_B + so, vbh + go);
        }
    };
    auto store_mask = [&](int j) {
        if (tid < 16) {
            uint32_t v = *(const uint32_t*)(mask + (size_t)b * S_ + j * 64 + tid * 4);
            *(uint32_t*)(sm + FMS_OFF + (j & 1) * 64 + tid * 4) = v;
        }
    };

    #pragma unroll
    for (int i = 0; i < 4; i++) {
        int c = tid + i * 128;
        int row = c >> 3, col = c & 7;
        uint32_t so = row * FSTRIDE_B + col * 16;
        CP16(QH + so, qbh + (size_t)row * rs * 2 + col * 16);
        CP16(QL + so, qbl + (size_t)row * rs * 2 + col * 16);
    }
    load_kv(0); CP_COMMIT();
    store_mask(0);

    uint32_t qfh[4][4], qfl[4][4];
    float o[8][4] = {};
    float m0 = -1e30f, m1 = -1e30f, l0 = 0.0f, l1 = 0.0f;

    const uint32_t arow = (lane & 15), acs = (lane >> 4) * 16;
    const uint32_t brow = (lane & 7) + (lane >> 4) * 8, bcs = ((lane >> 3) & 1) * 16;

    for (int kt = 0; kt < S_ / 64; kt++) {
        CP_WAIT0();
        __syncthreads();
        if (kt == 0) {
            #pragma unroll
            for (int ks = 0; ks < 4; ks++) {
                ldsm4(qfh[ks], QH + (wid * 16 + arow) * FSTRIDE_B + ks * 32 + acs);
                ldsm4(qfl[ks], QL + (wid * 16 + arow) * FSTRIDE_B + ks * 32 + acs);
            }
        }
        if (kt + 1 < S_ / 64) { load_kv(kt + 1); CP_COMMIT(); store_mask(kt + 1); }

        uint32_t sb = STG + (kt & 1) * FSTAGE_B;
        uint32_t KH = sb, KL = sb + FTILE_B, VH = sb + 2 * FTILE_B;

        float s[8][4] = {};
        #pragma unroll
        for (int ks = 0; ks < 4; ks++) {
            uint32_t kh[4][4], kl[4][4];
            #pragma unroll
            for (int np = 0; np < 4; np++) {
                ldsm4(kh[np], KH + (np * 16 + brow) * FSTRIDE_B + ks * 32 + bcs);
                ldsm4(kl[np], KL + (np * 16 + brow) * FSTRIDE_B + ks * 32 + bcs);
            }
            #pragma unroll
            for (int np = 0; np < 4; np++) {
                mma16816(s[2 * np],     qfh[ks], &kh[np][0]);
                mma16816(s[2 * np + 1], qfh[ks], &kh[np][2]);
                mma16816(s[2 * np],     qfh[ks], &kl[np][0]);
                mma16816(s[2 * np + 1], qfh[ks], &kl[np][2]);
                mma16816(s[2 * np],     qfl[ks], &kh[np][0]);
                mma16816(s[2 * np + 1], qfl[ks], &kh[np][2]);
            }
        }

        const float CM = SCALE_ * LOG2E_;
        float rmax0 = -1e30f, rmax1 = -1e30f;
        #pragma unroll
        for (int nt = 0; nt < 8; nt++) {
            unsigned short mm = *(const unsigned short*)(sm + FMS_OFF + (kt & 1) * 64 + nt * 8 + (lane & 3) * 2);
            bool k0m = (mm & 0xFF) != 0, k1m = (mm >> 8) != 0;
            s[nt][0] = k0m ? TNEG_ : s[nt][0] * CM;
            s[nt][1] = k1m ? TNEG_ : s[nt][1] * CM;
            s[nt][2] = k0m ? TNEG_ : s[nt][2] * CM;
            s[nt][3] = k1m ? TNEG_ : s[nt][3] * CM;
            rmax0 = fmaxf(rmax0, fmaxf(s[nt][0], s[nt][1]));
            rmax1 = fmaxf(rmax1, fmaxf(s[nt][2], s[nt][3]));
        }
        rmax0 = fmaxf(rmax0, __shfl_xor_sync(0xffffffffu, rmax0, 1));
        rmax0 = fmaxf(rmax0, __shfl_xor_sync(0xffffffffu, rmax0, 2));
        rmax1 = fmaxf(rmax1, __shfl_xor_sync(0xffffffffu, rmax1, 1));
        rmax1 = fmaxf(rmax1, __shfl_xor_sync(0xffffffffu, rmax1, 2));
        float mn0 = fmaxf(m0, rmax0), mn1 = fmaxf(m1, rmax1);
        float cr0 = ex2(m0 - mn0), cr1 = ex2(m1 - mn1);
        m0 = mn0; m1 = mn1;
        float ps0 = 0.0f, ps1 = 0.0f;
        #pragma unroll
        for (int nt = 0; nt < 8; nt++) {
            s[nt][0] = ex2(s[nt][0] - mn0);
            s[nt][1] = ex2(s[nt][1] - mn0);
            s[nt][2] = ex2(s[nt][2] - mn1);
            s[nt][3] = ex2(s[nt][3] - mn1);
            ps0 += s[nt][0] + s[nt][1];
            ps1 += s[nt][2] + s[nt][3];
        }
        ps0 += __shfl_xor_sync(0xffffffffu, ps0, 1);
        ps0 += __shfl_xor_sync(0xffffffffu, ps0, 2);
        ps1 += __shfl_xor_sync(0xffffffffu, ps1, 1);
        ps1 += __shfl_xor_sync(0xffffffffu, ps1, 2);
        l0 = l0 * cr0 + ps0;
        l1 = l1 * cr1 + ps1;
        #pragma unroll
        for (int nt = 0; nt < 8; nt++) {
            o[nt][0] *= cr0; o[nt][1] *= cr0;
            o[nt][2] *= cr1; o[nt][3] *= cr1;
        }

        uint32_t ph[4][4];
        #pragma unroll
        for (int kp = 0; kp < 4; kp++) {
            ph[kp][0] = packh2(s[2 * kp][0],     s[2 * kp][1]);
            ph[kp][1] = packh2(s[2 * kp][2],     s[2 * kp][3]);
            ph[kp][2] = packh2(s[2 * kp + 1][0], s[2 * kp + 1][1]);
            ph[kp][3] = packh2(s[2 * kp + 1][2], s[2 * kp + 1][3]);
        }

        #pragma unroll
        for (int kp = 0; kp < 4; kp++) {
            uint32_t vh[4][4];
            uint32_t krow = kp * 16 + (lane & 15);
            uint32_t dbyte = (lane >> 4) * 16;
            #pragma unroll
            for (int dp = 0; dp < 4; dp++)
                ldsm4t(vh[dp], VH + krow * FSTRIDE_B + dp * 32 + dbyte);
            #pragma unroll
            for (int dp = 0; dp < 4; dp++) {
                mma16816(o[2 * dp],     ph[kp], &vh[dp][0]);
                mma16816(o[2 * dp + 1], ph[kp], &vh[dp][2]);
            }
        }
    }

    float il0 = 1.0f / l0, il1 = 1.0f / l1;
    int r0 = q0 + wid * 16 + (lane >> 2);
    int cbase = h * 64 + (lane & 3) * 2;
    #pragma unroll
    for (int nt = 0; nt < 8; nt++) {
        int c = cbase + nt * 8;
        size_t i0 = ((size_t)b * S_ + r0) * D_ + c;
        *(uint32_t*)(cth + i0) = packh2(o[nt][0] * il0, o[nt][1] * il0);
        size_t i1 = i0 + 8 * D_;
        *(uint32_t*)(cth + i1) = packh2(o[nt][2] * il1, o[nt][3] * il1);
    }
}

// ---------------- launch ----------------
extern "C" void kernel_launch(void* const* d_in, const int* in_sizes, int n_in,
                              void* d_out, int out_size)
{
    const float* x    = (const float*)d_in[0];
    const float* Wqkv = (const float*)d_in[1];
    const float* Wout = (const float*)d_in[2];
    const unsigned char* mask = (const unsigned char*)d_in[3];
    float* out = (float*)d_out;

    __half *xh, *xl, *wqh, *wql, *woh, *qvh, *qvl, *cth;
    cudaGetSymbolAddress((void**)&xh,  g_xh);
    cudaGetSymbolAddress((void**)&xl,  g_xl);
    cudaGetSymbolAddress((void**)&wqh, g_wqh);
    cudaGetSymbolAddress((void**)&wql, g_wql);
    cudaGetSymbolAddress((void**)&woh, g_woh);
    cudaGetSymbolAddress((void**)&qvh, g_qkvh);
    cudaGetSymbolAddress((void**)&qvl, g_qkvl);
    cudaGetSymbolAddress((void**)&cth, g_cth);

    const int g3_smem = 2 * G3STAGE_B;   // 81920 -> 2 CTAs/SM
    const int g1_smem = 2 * G1STAGE_B;   // 40960
    const int flash_smem = FSMEM_TOTAL;
    static int attrs_set = 0;
    if (!attrs_set) {
        cudaFuncSetAttribute(gemm3, cudaFuncAttributeMaxDynamicSharedMemorySize, g3_smem);
        cudaFuncSetAttribute(gemm1, cudaFuncAttributeMaxDynamicSharedMemorySize, g1_smem);
        cudaFuncSetAttribute(flash_mma, cudaFuncAttributeMaxDynamicSharedMemorySize, flash_smem);
        attrs_set = 1;
    }

    // 0) splits (unscaled residuals)
    {
        int n4x = (B_ * S_ * D_) / 4;
        split_pair<<<(n4x + 255) / 256, 256>>>(x, xh, xl, n4x);
        int n4w = (3 * D_ * D_) / 4;
        split_pair<<<(n4w + 255) / 256, 256>>>(Wqkv, wqh, wql, n4w);
        int n4o = (D_ * D_) / 4;
        split_hi<<<(n4o + 255) / 256, 256>>>(Wout, woh, n4o);
    }

    // 1a) Q,K = x @ Wqkv[0:2D]^T  (3-term)
    {
        dim3 grid((2 * D_) / 128, (B_ * S_) / 128);
        gemm3<<<grid, 256, g3_smem>>>(xh, xl, wqh, wql, qvh, qvl, 3 * D_, D_);
    }
    // 1b) V = x @ Wqkv[2D:3D]^T  (1-term)
    {
        dim3 grid(D_ / 128, (B_ * S_) / 128);
        gemm1<<<grid, 256, g1_smem>>>(xh, wqh + (size_t)2 * D_ * D_,
                                      nullptr, qvh + 2 * D_, 3 * D_, D_, 1);
    }
    // 2) flash attention -> ctx fp16
    {
        dim3 grid(S_ / 64, B_ * H_);
        flash_mma<<<grid, 128, flash_smem>>>(qvh, qvl, mask, cth);
    }
    // 3) out = ctx @ Wout^T (1-term) -> f32
    {
        dim3 grid(D_ / 128, (B_ * S_) / 128);
        gemm1<<<grid, 256, g1_smem>>>(cth, woh, out, nullptr, D_, D_, 0);
    }
}

// round 16
// speedup vs baseline: 1.9250x; 1.1460x over previous
#include <cuda_runtime.h>
#include <cuda_fp16.h>
#include <math.h>
#include <stdint.h>

#define B_  2
#define S_  2048
#define D_  1024
#define H_  16
#define DK_ 64
#define SCALE_ 0.125f
#define LOG2E_ 1.44269504f
#define TNEG_ (-86562.0f)   // -60000 * log2(e)

// ---------------- scratch ----------------
__device__ __half g_xh[B_ * S_ * D_];
__device__ __half g_wqh[3 * D_ * D_];
__device__ __half g_wql[3 * D_ * D_];          // unscaled residual
__device__ __half g_woh[D_ * D_];
__device__ __half g_qkvh[B_ * S_ * 3 * D_];
__device__ __half g_qkvl[B_ * S_ * 3 * D_];    // only K-region lo consumed
__device__ __half g_cth[B_ * S_ * D_];

// ================= helpers =================
__device__ __forceinline__ uint32_t smem_u32(const void* p) {
    uint32_t a;
    asm("{ .reg .u64 t; cvta.to.shared.u64 t, %1; cvt.u32.u64 %0, t; }" : "=r"(a) : "l"(p));
    return a;
}
#define CP16(dst, src) asm volatile("cp.async.cg.shared.global [%0], [%1], 16;" :: "r"(dst), "l"(src) : "memory")
#define CP_COMMIT()    asm volatile("cp.async.commit_group;" ::: "memory")
#define CP_WAIT0()     asm volatile("cp.async.wait_group 0;" ::: "memory")

__device__ __forceinline__ void ldsm4(uint32_t* r, uint32_t addr) {
    asm volatile("ldmatrix.sync.aligned.m8n8.x4.shared.b16 {%0,%1,%2,%3}, [%4];"
        : "=r"(r[0]), "=r"(r[1]), "=r"(r[2]), "=r"(r[3]) : "r"(addr));
}
__device__ __forceinline__ void ldsm4t(uint32_t* r, uint32_t addr) {
    asm volatile("ldmatrix.sync.aligned.m8n8.x4.trans.shared.b16 {%0,%1,%2,%3}, [%4];"
        : "=r"(r[0]), "=r"(r[1]), "=r"(r[2]), "=r"(r[3]) : "r"(addr));
}
__device__ __forceinline__ void mma16816(float* d, const uint32_t* a, const uint32_t* b) {
    asm volatile("mma.sync.aligned.m16n8k16.row.col.f32.f16.f16.f32 "
        "{%0,%1,%2,%3}, {%4,%5,%6,%7}, {%8,%9}, {%0,%1,%2,%3};"
        : "+f"(d[0]), "+f"(d[1]), "+f"(d[2]), "+f"(d[3])
        : "r"(a[0]), "r"(a[1]), "r"(a[2]), "r"(a[3]), "r"(b[0]), "r"(b[1]));
}
__device__ __forceinline__ float ex2(float x) {
    float y; asm("ex2.approx.ftz.f32 %0, %1;" : "=f"(y) : "f"(x)); return y;
}
__device__ __forceinline__ uint32_t packh2(float a, float b) {
    __half ha = __float2half_rn(a), hb = __float2half_rn(b);
    return (uint32_t)__half_as_ushort(ha) | ((uint32_t)__half_as_ushort(hb) << 16);
}
__device__ __forceinline__ void split2h(float a, float b, uint32_t& hi, uint32_t& lo) {
    __half ha = __float2half_rn(a), hb = __float2half_rn(b);
    hi = (uint32_t)__half_as_ushort(ha) | ((uint32_t)__half_as_ushort(hb) << 16);
    lo = packh2(a - __half2float(ha), b - __half2float(hb));
}

// ================= split kernels =================
__global__ void split_pair(const float* __restrict__ in, __half* __restrict__ hi,
                           __half* __restrict__ lo, int n4) {
    int i = blockIdx.x * blockDim.x + threadIdx.x;
    if (i >= n4) return;
    float4 v = ((const float4*)in)[i];
    uint32_t h0, l0, h1, l1;
    split2h(v.x, v.y, h0, l0);
    split2h(v.z, v.w, h1, l1);
    ((uint2*)hi)[i] = make_uint2(h0, h1);
    ((uint2*)lo)[i] = make_uint2(l0, l1);
}
__global__ void split_hi(const float* __restrict__ in, __half* __restrict__ hi, int n4) {
    int i = blockIdx.x * blockDim.x + threadIdx.x;
    if (i >= n4) return;
    float4 v = ((const float4*)in)[i];
    ((uint2*)hi)[i] = make_uint2(packh2(v.x, v.y), packh2(v.z, v.w));
}

// ================= 2-term GEMM: C = Ah (Bh + Bl)^T, fp32 accum =================
// 128x128 tile, BK=32, 256 threads, 2-stage, 2 CTAs/SM.
#define GSTRIDE_B 80
#define GTILE_B (128 * GSTRIDE_B)       // 10240
#define G2STAGE_B (3 * GTILE_B)         // Ah, Bh, Bl

__global__ __launch_bounds__(256, 2)
void gemm2(const __half* __restrict__ Ah,
           const __half* __restrict__ Bh, const __half* __restrict__ Bl,
           __half* __restrict__ Ch, __half* __restrict__ Cl, int ldc, int K)
{
    extern __shared__ char sm[];
    const int tid = threadIdx.x, wid = tid >> 5, lane = tid & 31;
    const int wm = wid & 3, wn = wid >> 2;
    uint32_t sbase = smem_u32(sm);

    const char* gt[3];
    gt[0] = (const char*)(Ah + (size_t)blockIdx.y * 128 * K);
    gt[1] = (const char*)(Bh + (size_t)blockIdx.x * 128 * K);
    gt[2] = (const char*)(Bl + (size_t)blockIdx.x * 128 * K);

    float acc[2][8][4] = {};

    const int lrow = tid >> 2, lcol = tid & 3;
    auto load_stage = [&](int j) {
        uint32_t sb = sbase + (j & 1) * G2STAGE_B;
        const size_t gc = (size_t)j * 64;
        #pragma unroll
        for (int t = 0; t < 3; t++) {
            const char* g = gt[t] + gc;
            uint32_t tb = sb + t * GTILE_B;
            #pragma unroll
            for (int i = 0; i < 2; i++) {
                int row = lrow + i * 64;
                CP16(tb + row * GSTRIDE_B + lcol * 16,
                     g + (size_t)row * K * 2 + lcol * 16);
            }
        }
    };

    load_stage(0); CP_COMMIT();
    const int NK = K / 32;

    const uint32_t arow = (lane & 15), acs = (lane >> 4) * 16;
    const uint32_t brow = (lane & 7) + (lane >> 4) * 8, bcs = ((lane >> 3) & 1) * 16;

    for (int j = 0; j < NK; j++) {
        CP_WAIT0();
        __syncthreads();
        if (j + 1 < NK) { load_stage(j + 1); CP_COMMIT(); }

        uint32_t sb = sbase + (j & 1) * G2STAGE_B;
        uint32_t aH = sb + wm * 32 * GSTRIDE_B;
        uint32_t bH = sb + GTILE_B + wn * 64 * GSTRIDE_B;
        uint32_t bL = bH + GTILE_B;

        #pragma unroll
        for (int ks = 0; ks < 2; ks++) {
            uint32_t ah[2][4];
            #pragma unroll
            for (int mt = 0; mt < 2; mt++)
                ldsm4(ah[mt], aH + (mt * 16 + arow) * GSTRIDE_B + ks * 32 + acs);
            #pragma unroll
            for (int np = 0; np < 4; np++) {
                uint32_t bh[4], bl[4];
                ldsm4(bh, bH + (np * 16 + brow) * GSTRIDE_B + ks * 32 + bcs);
                ldsm4(bl, bL + (np * 16 + brow) * GSTRIDE_B + ks * 32 + bcs);
                #pragma unroll
                for (int mt = 0; mt < 2; mt++) {
                    mma16816(acc[mt][2 * np],     ah[mt], &bh[0]);
                    mma16816(acc[mt][2 * np + 1], ah[mt], &bh[2]);
                    mma16816(acc[mt][2 * np],     ah[mt], &bl[0]);
                    mma16816(acc[mt][2 * np + 1], ah[mt], &bl[2]);
                }
            }
        }
    }

    const int rb = blockIdx.y * 128 + wm * 32 + (lane >> 2);
    const int cb = blockIdx.x * 128 + wn * 64 + (lane & 3) * 2;
    #pragma unroll
    for (int mt = 0; mt < 2; mt++)
        #pragma unroll
        for (int half = 0; half < 2; half++) {
            int r = rb + mt * 16 + half * 8;
            #pragma unroll
            for (int nt = 0; nt < 8; nt++) {
                int c = cb + nt * 8;
                uint32_t hi, lo;
                split2h(acc[mt][nt][half * 2 + 0], acc[mt][nt][half * 2 + 1], hi, lo);
                *(uint32_t*)(Ch + (size_t)r * ldc + c) = hi;
                *(uint32_t*)(Cl + (size_t)r * ldc + c) = lo;
            }
        }
}

// ================= 1-term fp16 GEMM =================
#define G1STAGE_B (2 * GTILE_B)

__global__ __launch_bounds__(256, 2)
void gemm1(const __half* __restrict__ Ah, const __half* __restrict__ Bh,
           float* __restrict__ Cf, __half* __restrict__ Ch, int ldc, int K, int fp16out)
{
    extern __shared__ char sm[];
    const int tid = threadIdx.x, wid = tid >> 5, lane = tid & 31;
    const int wm = wid & 3, wn = wid >> 2;
    uint32_t sbase = smem_u32(sm);

    const char* gA = (const char*)(Ah + (size_t)blockIdx.y * 128 * K);
    const char* gB = (const char*)(Bh + (size_t)blockIdx.x * 128 * K);

    float acc[2][8][4] = {};

    const int lrow = tid >> 2, lcol = tid & 3;
    auto load_stage = [&](int j) {
        uint32_t sb = sbase + (j & 1) * G1STAGE_B;
        const size_t gc = (size_t)j * 64;
        #pragma unroll
        for (int i = 0; i < 2; i++) {
            int row = lrow + i * 64;
            uint32_t so = row * GSTRIDE_B + lcol * 16;
            size_t go = gc + (size_t)row * K * 2 + lcol * 16;
            CP16(sb + so, gA + go);
            CP16(sb + GTILE_B + so, gB + go);
        }
    };

    load_stage(0); CP_COMMIT();
    const int NK = K / 32;

    const uint32_t arow = (lane & 15), acs = (lane >> 4) * 16;
    const uint32_t brow = (lane & 7) + (lane >> 4) * 8, bcs = ((lane >> 3) & 1) * 16;

    for (int j = 0; j < NK; j++) {
        CP_WAIT0();
        __syncthreads();
        if (j + 1 < NK) { load_stage(j + 1); CP_COMMIT(); }

        uint32_t sb = sbase + (j & 1) * G1STAGE_B;
        uint32_t aH = sb + wm * 32 * GSTRIDE_B;
        uint32_t bH = sb + GTILE_B + wn * 64 * GSTRIDE_B;

        #pragma unroll
        for (int ks = 0; ks < 2; ks++) {
            uint32_t ah[2][4];
            #pragma unroll
            for (int mt = 0; mt < 2; mt++)
                ldsm4(ah[mt], aH + (mt * 16 + arow) * GSTRIDE_B + ks * 32 + acs);
            #pragma unroll
            for (int np = 0; np < 4; np++) {
                uint32_t bh[4];
                ldsm4(bh, bH + (np * 16 + brow) * GSTRIDE_B + ks * 32 + bcs);
                #pragma unroll
                for (int mt = 0; mt < 2; mt++) {
                    mma16816(acc[mt][2 * np],     ah[mt], &bh[0]);
                    mma16816(acc[mt][2 * np + 1], ah[mt], &bh[2]);
                }
            }
        }
    }

    const int rb = blockIdx.y * 128 + wm * 32 + (lane >> 2);
    const int cb = blockIdx.x * 128 + wn * 64 + (lane & 3) * 2;
    #pragma unroll
    for (int mt = 0; mt < 2; mt++)
        #pragma unroll
        for (int half = 0; half < 2; half++) {
            int r = rb + mt * 16 + half * 8;
            #pragma unroll
            for (int nt = 0; nt < 8; nt++) {
                int c = cb + nt * 8;
                float v0 = acc[mt][nt][half * 2 + 0];
                float v1 = acc[mt][nt][half * 2 + 1];
                if (fp16out)
                    *(uint32_t*)(Ch + (size_t)r * ldc + c) = packh2(v0, v1);
                else
                    *(float2*)(Cf + (size_t)r * ldc + c) = make_float2(v0, v1);
            }
        }
}

// ================= flash attention: S 2-term (qh·kh + qh·kl), PV 1-term =================
#define FSTRIDE_B 144
#define FTILE_B (64 * FSTRIDE_B)        // 9216
#define FSTAGE_B (3 * FTILE_B)          // Kh, Kl, Vh
#define FQ_OFF 0
#define FST_OFF FTILE_B                 // Q hi only
#define FMS_OFF (FST_OFF + 2 * FSTAGE_B)
#define FSMEM_TOTAL (FMS_OFF + 128)

__global__ __launch_bounds__(128, 2)
void flash_mma(const __half* __restrict__ qh, const __half* __restrict__ ql,
               const unsigned char* __restrict__ mask, __half* __restrict__ cth)
{
    extern __shared__ char sm[];
    const int tid = threadIdx.x, wid = tid >> 5, lane = tid & 31;
    const int bh_ = blockIdx.y, b = bh_ >> 4, h = bh_ & 15;
    const int q0 = blockIdx.x * 64;
    uint32_t sbase = smem_u32(sm);
    const uint32_t QH = sbase + FQ_OFF;
    const uint32_t STG = sbase + FST_OFF;

    const size_t rs = 3 * D_;
    const char* qbh = (const char*)(qh + ((size_t)b * S_ + q0) * rs + h * 64);
    const char* kbh = (const char*)(qh + (size_t)b * S_ * rs + D_ + h * 64);
    const char* kbl = (const char*)(ql + (size_t)b * S_ * rs + D_ + h * 64);
    const char* vbh = (const char*)(qh + (size_t)b * S_ * rs + 2 * D_ + h * 64);

    auto load_kv = [&](int j) {
        uint32_t sb = STG + (j & 1) * FSTAGE_B;
        size_t gk = (size_t)j * 64 * rs * 2;
        #pragma unroll
        for (int i = 0; i < 4; i++) {
            int c = tid + i * 128;
            int row = c >> 3, col = c & 7;
            size_t go = gk + (size_t)row * rs * 2 + col * 16;
            uint32_t so = row * FSTRIDE_B + col * 16;
            CP16(sb + 0 * FTILE_B + so, kbh + go);
            CP16(sb + 1 * FTILE_B + so, kbl + go);
            CP16(sb + 2 * FTILE_B + so, vbh + go);
        }
    };
    auto store_mask = [&](int j) {
        if (tid < 16) {
            uint32_t v = *(const uint32_t*)(mask + (size_t)b * S_ + j * 64 + tid * 4);
            *(uint32_t*)(sm + FMS_OFF + (j & 1) * 64 + tid * 4) = v;
        }
    };

    #pragma unroll
    for (int i = 0; i < 4; i++) {
        int c = tid + i * 128;
        int row = c >> 3, col = c & 7;
        CP16(QH + row * FSTRIDE_B + col * 16, qbh + (size_t)row * rs * 2 + col * 16);
    }
    load_kv(0); CP_COMMIT();
    store_mask(0);

    uint32_t qfh[4][4];
    float o[8][4] = {};
    float m0 = -1e30f, m1 = -1e30f, l0 = 0.0f, l1 = 0.0f;

    const uint32_t arow = (lane & 15), acs = (lane >> 4) * 16;
    const uint32_t brow = (lane & 7) + (lane >> 4) * 8, bcs = ((lane >> 3) & 1) * 16;

    for (int kt = 0; kt < S_ / 64; kt++) {
        CP_WAIT0();
        __syncthreads();
        if (kt == 0) {
            #pragma unroll
            for (int ks = 0; ks < 4; ks++)
                ldsm4(qfh[ks], QH + (wid * 16 + arow) * FSTRIDE_B + ks * 32 + acs);
        }
        if (kt + 1 < S_ / 64) { load_kv(kt + 1); CP_COMMIT(); store_mask(kt + 1); }

        uint32_t sb = STG + (kt & 1) * FSTAGE_B;
        uint32_t KH = sb, KL = sb + FTILE_B, VH = sb + 2 * FTILE_B;

        // ---- S = Q K^T, 2-term: qh·(kh + kl) ----
        float s[8][4] = {};
        #pragma unroll
        for (int ks = 0; ks < 4; ks++) {
            uint32_t kh[4][4], kl[4][4];
            #pragma unroll
            for (int np = 0; np < 4; np++) {
                ldsm4(kh[np], KH + (np * 16 + brow) * FSTRIDE_B + ks * 32 + bcs);
                ldsm4(kl[np], KL + (np * 16 + brow) * FSTRIDE_B + ks * 32 + bcs);
            }
            #pragma unroll
            for (int np = 0; np < 4; np++) {
                mma16816(s[2 * np],     qfh[ks], &kh[np][0]);
                mma16816(s[2 * np + 1], qfh[ks], &kh[np][2]);
                mma16816(s[2 * np],     qfh[ks], &kl[np][0]);
                mma16816(s[2 * np + 1], qfh[ks], &kl[np][2]);
            }
        }

        // ---- softmax (exp2 domain) ----
        const float CM = SCALE_ * LOG2E_;
        float rmax0 = -1e30f, rmax1 = -1e30f;
        #pragma unroll
        for (int nt = 0; nt < 8; nt++) {
            unsigned short mm = *(const unsigned short*)(sm + FMS_OFF + (kt & 1) * 64 + nt * 8 + (lane & 3) * 2);
            bool k0m = (mm & 0xFF) != 0, k1m = (mm >> 8) != 0;
            s[nt][0] = k0m ? TNEG_ : s[nt][0] * CM;
            s[nt][1] = k1m ? TNEG_ : s[nt][1] * CM;
            s[nt][2] = k0m ? TNEG_ : s[nt][2] * CM;
            s[nt][3] = k1m ? TNEG_ : s[nt][3] * CM;
            rmax0 = fmaxf(rmax0, fmaxf(s[nt][0], s[nt][1]));
            rmax1 = fmaxf(rmax1, fmaxf(s[nt][2], s[nt][3]));
        }
        rmax0 = fmaxf(rmax0, __shfl_xor_sync(0xffffffffu, rmax0, 1));
        rmax0 = fmaxf(rmax0, __shfl_xor_sync(0xffffffffu, rmax0, 2));
        rmax1 = fmaxf(rmax1, __shfl_xor_sync(0xffffffffu, rmax1, 1));
        rmax1 = fmaxf(rmax1, __shfl_xor_sync(0xffffffffu, rmax1, 2));
        float mn0 = fmaxf(m0, rmax0), mn1 = fmaxf(m1, rmax1);
        float cr0 = ex2(m0 - mn0), cr1 = ex2(m1 - mn1);
        m0 = mn0; m1 = mn1;
        float ps0 = 0.0f, ps1 = 0.0f;
        #pragma unroll
        for (int nt = 0; nt < 8; nt++) {
            s[nt][0] = ex2(s[nt][0] - mn0);
            s[nt][1] = ex2(s[nt][1] - mn0);
            s[nt][2] = ex2(s[nt][2] - mn1);
            s[nt][3] = ex2(s[nt][3] - mn1);
            ps0 += s[nt][0] + s[nt][1];
            ps1 += s[nt][2] + s[nt][3];
        }
        ps0 += __shfl_xor_sync(0xffffffffu, ps0, 1);
        ps0 += __shfl_xor_sync(0xffffffffu, ps0, 2);
        ps1 += __shfl_xor_sync(0xffffffffu, ps1, 1);
        ps1 += __shfl_xor_sync(0xffffffffu, ps1, 2);
        l0 = l0 * cr0 + ps0;
        l1 = l1 * cr1 + ps1;
        #pragma unroll
        for (int nt = 0; nt < 8; nt++) {
            o[nt][0] *= cr0; o[nt][1] *= cr0;
            o[nt][2] *= cr1; o[nt][3] *= cr1;
        }

        uint32_t ph[4][4];
        #pragma unroll
        for (int kp = 0; kp < 4; kp++) {
            ph[kp][0] = packh2(s[2 * kp][0],     s[2 * kp][1]);
            ph[kp][1] = packh2(s[2 * kp][2],     s[2 * kp][3]);
            ph[kp][2] = packh2(s[2 * kp + 1][0], s[2 * kp + 1][1]);
            ph[kp][3] = packh2(s[2 * kp + 1][2], s[2 * kp + 1][3]);
        }

        // ---- O += P V, 1-term ----
        #pragma unroll
        for (int kp = 0; kp < 4; kp++) {
            uint32_t vh[4][4];
            uint32_t krow = kp * 16 + (lane & 15);
            uint32_t dbyte = (lane >> 4) * 16;
            #pragma unroll
            for (int dp = 0; dp < 4; dp++)
                ldsm4t(vh[dp], VH + krow * FSTRIDE_B + dp * 32 + dbyte);
            #pragma unroll
            for (int dp = 0; dp < 4; dp++) {
                mma16816(o[2 * dp],     ph[kp], &vh[dp][0]);
                mma16816(o[2 * dp + 1], ph[kp], &vh[dp][2]);
            }
        }
    }

    float il0 = 1.0f / l0, il1 = 1.0f / l1;
    int r0 = q0 + wid * 16 + (lane >> 2);
    int cbase = h * 64 + (lane & 3) * 2;
    #pragma unroll
    for (int nt = 0; nt < 8; nt++) {
        int c = cbase + nt * 8;
        size_t i0 = ((size_t)b * S_ + r0) * D_ + c;
        *(uint32_t*)(cth + i0) = packh2(o[nt][0] * il0, o[nt][1] * il0);
        size_t i1 = i0 + 8 * D_;
        *(uint32_t*)(cth + i1) = packh2(o[nt][2] * il1, o[nt][3] * il1);
    }
}

// ---------------- launch ----------------
extern "C" void kernel_launch(void* const* d_in, const int* in_sizes, int n_in,
                              void* d_out, int out_size)
{
    const float* x    = (const float*)d_in[0];
    const float* Wqkv = (const float*)d_in[1];
    const float* Wout = (const float*)d_in[2];
    const unsigned char* mask = (const unsigned char*)d_in[3];
    float* out = (float*)d_out;

    __half *xh, *wqh, *wql, *woh, *qvh, *qvl, *cth;
    cudaGetSymbolAddress((void**)&xh,  g_xh);
    cudaGetSymbolAddress((void**)&wqh, g_wqh);
    cudaGetSymbolAddress((void**)&wql, g_wql);
    cudaGetSymbolAddress((void**)&woh, g_woh);
    cudaGetSymbolAddress((void**)&qvh, g_qkvh);
    cudaGetSymbolAddress((void**)&qvl, g_qkvl);
    cudaGetSymbolAddress((void**)&cth, g_cth);

    const int g2_smem = 2 * G2STAGE_B;   // 61440 -> 2 CTAs/SM
    const int g1_smem = 2 * G1STAGE_B;   // 40960
    const int flash_smem = FSMEM_TOTAL;  // 64640 -> 2 CTAs/SM
    static int attrs_set = 0;
    if (!attrs_set) {
        cudaFuncSetAttribute(gemm2, cudaFuncAttributeMaxDynamicSharedMemorySize, g2_smem);
        cudaFuncSetAttribute(gemm1, cudaFuncAttributeMaxDynamicSharedMemorySize, g1_smem);
        cudaFuncSetAttribute(flash_mma, cudaFuncAttributeMaxDynamicSharedMemorySize, flash_smem);
        attrs_set = 1;
    }

    // 0) splits: x hi-only; Wqkv hi+lo; Wout hi-only
    {
        int n4x = (B_ * S_ * D_) / 4;
        split_hi<<<(n4x + 255) / 256, 256>>>(x, xh, n4x);
        int n4w = (3 * D_ * D_) / 4;
        split_pair<<<(n4w + 255) / 256, 256>>>(Wqkv, wqh, wql, n4w);
        int n4o = (D_ * D_) / 4;
        split_hi<<<(n4o + 255) / 256, 256>>>(Wout, woh, n4o);
    }

    // 1a) Q,K = xh @ (Wh+Wl)[0:2D]^T  (2-term) -> qkv hi/lo
    {
        dim3 grid((2 * D_) / 128, (B_ * S_) / 128);
        gemm2<<<grid, 256, g2_smem>>>(xh, wqh, wql, qvh, qvl, 3 * D_, D_);
    }
    // 1b) V = xh @ Wv_hi^T  (1-term)
    {
        dim3 grid(D_ / 128, (B_ * S_) / 128);
        gemm1<<<grid, 256, g1_smem>>>(xh, wqh + (size_t)2 * D_ * D_,
                                      nullptr, qvh + 2 * D_, 3 * D_, D_, 1);
    }
    // 2) flash attention -> ctx fp16
    {
        dim3 grid(S_ / 64, B_ * H_);
        flash_mma<<<grid, 128, flash_smem>>>(qvh, qvl, mask, cth);
    }
    // 3) out = ctx @ Wout^T (1-term) -> f32
    {
        dim3 grid(D_ / 128, (B_ * S_) / 128);
        gemm1<<<grid, 256, g1_smem>>>(cth, woh, out, nullptr, D_, D_, 0);
    }
}

// round 17
// speedup vs baseline: 2.5852x; 1.3430x over previous
#include <cuda_runtime.h>
#include <cuda_fp16.h>
#include <math.h>
#include <stdint.h>

#define B_  2
#define S_  2048
#define D_  1024
#define H_  16
#define DK_ 64
#define SCALE_ 0.125f
#define LOG2E_ 1.44269504f
#define TNEG_ (-86562.0f)   // -60000 * log2(e)

// ---------------- scratch ----------------
__device__ __half g_xh[B_ * S_ * D_];
__device__ __half g_wqh[3 * D_ * D_];
__device__ __half g_woh[D_ * D_];
__device__ __half g_qkvh[B_ * S_ * 3 * D_];
__device__ __half g_cth[B_ * S_ * D_];

// ================= helpers =================
__device__ __forceinline__ uint32_t smem_u32(const void* p) {
    uint32_t a;
    asm("{ .reg .u64 t; cvta.to.shared.u64 t, %1; cvt.u32.u64 %0, t; }" : "=r"(a) : "l"(p));
    return a;
}
#define CP16(dst, src) asm volatile("cp.async.cg.shared.global [%0], [%1], 16;" :: "r"(dst), "l"(src) : "memory")
#define CP_COMMIT()    asm volatile("cp.async.commit_group;" ::: "memory")
#define CP_WAIT0()     asm volatile("cp.async.wait_group 0;" ::: "memory")

__device__ __forceinline__ void ldsm4(uint32_t* r, uint32_t addr) {
    asm volatile("ldmatrix.sync.aligned.m8n8.x4.shared.b16 {%0,%1,%2,%3}, [%4];"
        : "=r"(r[0]), "=r"(r[1]), "=r"(r[2]), "=r"(r[3]) : "r"(addr));
}
__device__ __forceinline__ void ldsm4t(uint32_t* r, uint32_t addr) {
    asm volatile("ldmatrix.sync.aligned.m8n8.x4.trans.shared.b16 {%0,%1,%2,%3}, [%4];"
        : "=r"(r[0]), "=r"(r[1]), "=r"(r[2]), "=r"(r[3]) : "r"(addr));
}
__device__ __forceinline__ void mma16816(float* d, const uint32_t* a, const uint32_t* b) {
    asm volatile("mma.sync.aligned.m16n8k16.row.col.f32.f16.f16.f32 "
        "{%0,%1,%2,%3}, {%4,%5,%6,%7}, {%8,%9}, {%0,%1,%2,%3};"
        : "+f"(d[0]), "+f"(d[1]), "+f"(d[2]), "+f"(d[3])
        : "r"(a[0]), "r"(a[1]), "r"(a[2]), "r"(a[3]), "r"(b[0]), "r"(b[1]));
}
__device__ __forceinline__ float ex2(float x) {
    float y; asm("ex2.approx.ftz.f32 %0, %1;" : "=f"(y) : "f"(x)); return y;
}
__device__ __forceinline__ uint32_t packh2(float a, float b) {
    __half ha = __float2half_rn(a), hb = __float2half_rn(b);
    return (uint32_t)__half_as_ushort(ha) | ((uint32_t)__half_as_ushort(hb) << 16);
}

// ================= split fp32 -> fp16 =================
__global__ void split_hi(const float* __restrict__ in, __half* __restrict__ hi, int n4) {
    int i = blockIdx.x * blockDim.x + threadIdx.x;
    if (i >= n4) return;
    float4 v = ((const float4*)in)[i];
    ((uint2*)hi)[i] = make_uint2(packh2(v.x, v.y), packh2(v.z, v.w));
}

// ================= 1-term fp16 GEMM =================
// 128x128 tile, BK=32, 256 threads, 2-stage, 2 CTAs/SM.
#define GSTRIDE_B 80
#define GTILE_B (128 * GSTRIDE_B)       // 10240
#define G1STAGE_B (2 * GTILE_B)

__global__ __launch_bounds__(256, 2)
void gemm1(const __half* __restrict__ Ah, const __half* __restrict__ Bh,
           float* __restrict__ Cf, __half* __restrict__ Ch, int ldc, int K, int fp16out)
{
    extern __shared__ char sm[];
    const int tid = threadIdx.x, wid = tid >> 5, lane = tid & 31;
    const int wm = wid & 3, wn = wid >> 2;
    uint32_t sbase = smem_u32(sm);

    const char* gA = (const char*)(Ah + (size_t)blockIdx.y * 128 * K);
    const char* gB = (const char*)(Bh + (size_t)blockIdx.x * 128 * K);

    float acc[2][8][4] = {};

    const int lrow = tid >> 2, lcol = tid & 3;
    auto load_stage = [&](int j) {
        uint32_t sb = sbase + (j & 1) * G1STAGE_B;
        const size_t gc = (size_t)j * 64;
        #pragma unroll
        for (int i = 0; i < 2; i++) {
            int row = lrow + i * 64;
            uint32_t so = row * GSTRIDE_B + lcol * 16;
            size_t go = gc + (size_t)row * K * 2 + lcol * 16;
            CP16(sb + so, gA + go);
            CP16(sb + GTILE_B + so, gB + go);
        }
    };

    load_stage(0); CP_COMMIT();
    const int NK = K / 32;

    const uint32_t arow = (lane & 15), acs = (lane >> 4) * 16;
    const uint32_t brow = (lane & 7) + (lane >> 4) * 8, bcs = ((lane >> 3) & 1) * 16;

    for (int j = 0; j < NK; j++) {
        CP_WAIT0();
        __syncthreads();
        if (j + 1 < NK) { load_stage(j + 1); CP_COMMIT(); }

        uint32_t sb = sbase + (j & 1) * G1STAGE_B;
        uint32_t aH = sb + wm * 32 * GSTRIDE_B;
        uint32_t bH = sb + GTILE_B + wn * 64 * GSTRIDE_B;

        #pragma unroll
        for (int ks = 0; ks < 2; ks++) {
            uint32_t ah[2][4];
            #pragma unroll
            for (int mt = 0; mt < 2; mt++)
                ldsm4(ah[mt], aH + (mt * 16 + arow) * GSTRIDE_B + ks * 32 + acs);
            #pragma unroll
            for (int np = 0; np < 4; np++) {
                uint32_t bh[4];
                ldsm4(bh, bH + (np * 16 + brow) * GSTRIDE_B + ks * 32 + bcs);
                #pragma unroll
                for (int mt = 0; mt < 2; mt++) {
                    mma16816(acc[mt][2 * np],     ah[mt], &bh[0]);
                    mma16816(acc[mt][2 * np + 1], ah[mt], &bh[2]);
                }
            }
        }
    }

    const int rb = blockIdx.y * 128 + wm * 32 + (lane >> 2);
    const int cb = blockIdx.x * 128 + wn * 64 + (lane & 3) * 2;
    #pragma unroll
    for (int mt = 0; mt < 2; mt++)
        #pragma unroll
        for (int half = 0; half < 2; half++) {
            int r = rb + mt * 16 + half * 8;
            #pragma unroll
            for (int nt = 0; nt < 8; nt++) {
                int c = cb + nt * 8;
                float v0 = acc[mt][nt][half * 2 + 0];
                float v1 = acc[mt][nt][half * 2 + 1];
                if (fp16out)
                    *(uint32_t*)(Ch + (size_t)r * ldc + c) = packh2(v0, v1);
                else
                    *(float2*)(Cf + (size_t)r * ldc + c) = make_float2(v0, v1);
            }
        }
}

// ================= flash attention: pure fp16, 1-term S and PV =================
#define FSTRIDE_B 144
#define FTILE_B (64 * FSTRIDE_B)        // 9216
#define FSTAGE_B (2 * FTILE_B)          // Kh, Vh
#define FQ_OFF 0
#define FST_OFF FTILE_B
#define FMS_OFF (FST_OFF + 2 * FSTAGE_B)
#define FSMEM_TOTAL (FMS_OFF + 128)     // 46208

__global__ __launch_bounds__(128, 2)
void flash_mma(const __half* __restrict__ qh, const unsigned char* __restrict__ mask,
               __half* __restrict__ cth)
{
    extern __shared__ char sm[];
    const int tid = threadIdx.x, wid = tid >> 5, lane = tid & 31;
    const int bh_ = blockIdx.y, b = bh_ >> 4, h = bh_ & 15;
    const int q0 = blockIdx.x * 64;
    uint32_t sbase = smem_u32(sm);
    const uint32_t QH = sbase + FQ_OFF;
    const uint32_t STG = sbase + FST_OFF;

    const size_t rs = 3 * D_;
    const char* qbh = (const char*)(qh + ((size_t)b * S_ + q0) * rs + h * 64);
    const char* kbh = (const char*)(qh + (size_t)b * S_ * rs + D_ + h * 64);
    const char* vbh = (const char*)(qh + (size_t)b * S_ * rs + 2 * D_ + h * 64);

    auto load_kv = [&](int j) {
        uint32_t sb = STG + (j & 1) * FSTAGE_B;
        size_t gk = (size_t)j * 64 * rs * 2;
        #pragma unroll
        for (int i = 0; i < 4; i++) {
            int c = tid + i * 128;
            int row = c >> 3, col = c & 7;
            size_t go = gk + (size_t)row * rs * 2 + col * 16;
            uint32_t so = row * FSTRIDE_B + col * 16;
            CP16(sb + 0 * FTILE_B + so, kbh + go);
            CP16(sb + 1 * FTILE_B + so, vbh + go);
        }
    };
    auto store_mask = [&](int j) {
        if (tid < 16) {
            uint32_t v = *(const uint32_t*)(mask + (size_t)b * S_ + j * 64 + tid * 4);
            *(uint32_t*)(sm + FMS_OFF + (j & 1) * 64 + tid * 4) = v;
        }
    };

    #pragma unroll
    for (int i = 0; i < 4; i++) {
        int c = tid + i * 128;
        int row = c >> 3, col = c & 7;
        CP16(QH + row * FSTRIDE_B + col * 16, qbh + (size_t)row * rs * 2 + col * 16);
    }
    load_kv(0); CP_COMMIT();
    store_mask(0);

    uint32_t qfh[4][4];
    float o[8][4] = {};
    float m0 = -1e30f, m1 = -1e30f, l0 = 0.0f, l1 = 0.0f;

    const uint32_t arow = (lane & 15), acs = (lane >> 4) * 16;
    const uint32_t brow = (lane & 7) + (lane >> 4) * 8, bcs = ((lane >> 3) & 1) * 16;

    for (int kt = 0; kt < S_ / 64; kt++) {
        CP_WAIT0();
        __syncthreads();
        if (kt == 0) {
            #pragma unroll
            for (int ks = 0; ks < 4; ks++)
                ldsm4(qfh[ks], QH + (wid * 16 + arow) * FSTRIDE_B + ks * 32 + acs);
        }
        if (kt + 1 < S_ / 64) { load_kv(kt + 1); CP_COMMIT(); store_mask(kt + 1); }

        uint32_t sb = STG + (kt & 1) * FSTAGE_B;
        uint32_t KH = sb, VH = sb + FTILE_B;

        // ---- S = Q K^T, 1-term ----
        float s[8][4] = {};
        #pragma unroll
        for (int ks = 0; ks < 4; ks++) {
            uint32_t kh[4][4];
            #pragma unroll
            for (int np = 0; np < 4; np++)
                ldsm4(kh[np], KH + (np * 16 + brow) * FSTRIDE_B + ks * 32 + bcs);
            #pragma unroll
            for (int np = 0; np < 4; np++) {
                mma16816(s[2 * np],     qfh[ks], &kh[np][0]);
                mma16816(s[2 * np + 1], qfh[ks], &kh[np][2]);
            }
        }

        // ---- softmax (exp2 domain) ----
        const float CM = SCALE_ * LOG2E_;
        float rmax0 = -1e30f, rmax1 = -1e30f;
        #pragma unroll
        for (int nt = 0; nt < 8; nt++) {
            unsigned short mm = *(const unsigned short*)(sm + FMS_OFF + (kt & 1) * 64 + nt * 8 + (lane & 3) * 2);
            bool k0m = (mm & 0xFF) != 0, k1m = (mm >> 8) != 0;
            s[nt][0] = k0m ? TNEG_ : s[nt][0] * CM;
            s[nt][1] = k1m ? TNEG_ : s[nt][1] * CM;
            s[nt][2] = k0m ? TNEG_ : s[nt][2] * CM;
            s[nt][3] = k1m ? TNEG_ : s[nt][3] * CM;
            rmax0 = fmaxf(rmax0, fmaxf(s[nt][0], s[nt][1]));
            rmax1 = fmaxf(rmax1, fmaxf(s[nt][2], s[nt][3]));
        }
        rmax0 = fmaxf(rmax0, __shfl_xor_sync(0xffffffffu, rmax0, 1));
        rmax0 = fmaxf(rmax0, __shfl_xor_sync(0xffffffffu, rmax0, 2));
        rmax1 = fmaxf(rmax1, __shfl_xor_sync(0xffffffffu, rmax1, 1));
        rmax1 = fmaxf(rmax1, __shfl_xor_sync(0xffffffffu, rmax1, 2));
        float mn0 = fmaxf(m0, rmax0), mn1 = fmaxf(m1, rmax1);
        float cr0 = ex2(m0 - mn0), cr1 = ex2(m1 - mn1);
        m0 = mn0; m1 = mn1;
        float ps0 = 0.0f, ps1 = 0.0f;
        #pragma unroll
        for (int nt = 0; nt < 8; nt++) {
            s[nt][0] = ex2(s[nt][0] - mn0);
            s[nt][1] = ex2(s[nt][1] - mn0);
            s[nt][2] = ex2(s[nt][2] - mn1);
            s[nt][3] = ex2(s[nt][3] - mn1);
            ps0 += s[nt][0] + s[nt][1];
            ps1 += s[nt][2] + s[nt][3];
        }
        ps0 += __shfl_xor_sync(0xffffffffu, ps0, 1);
        ps0 += __shfl_xor_sync(0xffffffffu, ps0, 2);
        ps1 += __shfl_xor_sync(0xffffffffu, ps1, 1);
        ps1 += __shfl_xor_sync(0xffffffffu, ps1, 2);
        l0 = l0 * cr0 + ps0;
        l1 = l1 * cr1 + ps1;
        #pragma unroll
        for (int nt = 0; nt < 8; nt++) {
            o[nt][0] *= cr0; o[nt][1] *= cr0;
            o[nt][2] *= cr1; o[nt][3] *= cr1;
        }

        uint32_t ph[4][4];
        #pragma unroll
        for (int kp = 0; kp < 4; kp++) {
            ph[kp][0] = packh2(s[2 * kp][0],     s[2 * kp][1]);
            ph[kp][1] = packh2(s[2 * kp][2],     s[2 * kp][3]);
            ph[kp][2] = packh2(s[2 * kp + 1][0], s[2 * kp + 1][1]);
            ph[kp][3] = packh2(s[2 * kp + 1][2], s[2 * kp + 1][3]);
        }

        // ---- O += P V, 1-term ----
        #pragma unroll
        for (int kp = 0; kp < 4; kp++) {
            uint32_t vh[4][4];
            uint32_t krow = kp * 16 + (lane & 15);
            uint32_t dbyte = (lane >> 4) * 16;
            #pragma unroll
            for (int dp = 0; dp < 4; dp++)
                ldsm4t(vh[dp], VH + krow * FSTRIDE_B + dp * 32 + dbyte);
            #pragma unroll
            for (int dp = 0; dp < 4; dp++) {
                mma16816(o[2 * dp],     ph[kp], &vh[dp][0]);
                mma16816(o[2 * dp + 1], ph[kp], &vh[dp][2]);
            }
        }
    }

    float il0 = 1.0f / l0, il1 = 1.0f / l1;
    int r0 = q0 + wid * 16 + (lane >> 2);
    int cbase = h * 64 + (lane & 3) * 2;
    #pragma unroll
    for (int nt = 0; nt < 8; nt++) {
        int c = cbase + nt * 8;
        size_t i0 = ((size_t)b * S_ + r0) * D_ + c;
        *(uint32_t*)(cth + i0) = packh2(o[nt][0] * il0, o[nt][1] * il0);
        size_t i1 = i0 + 8 * D_;
        *(uint32_t*)(cth + i1) = packh2(o[nt][2] * il1, o[nt][3] * il1);
    }
}

// ---------------- launch ----------------
extern "C" void kernel_launch(void* const* d_in, const int* in_sizes, int n_in,
                              void* d_out, int out_size)
{
    const float* x    = (const float*)d_in[0];
    const float* Wqkv = (const float*)d_in[1];
    const float* Wout = (const float*)d_in[2];
    const unsigned char* mask = (const unsigned char*)d_in[3];
    float* out = (float*)d_out;

    __half *xh, *wqh, *woh, *qvh, *cth;
    cudaGetSymbolAddress((void**)&xh,  g_xh);
    cudaGetSymbolAddress((void**)&wqh, g_wqh);
    cudaGetSymbolAddress((void**)&woh, g_woh);
    cudaGetSymbolAddress((void**)&qvh, g_qkvh);
    cudaGetSymbolAddress((void**)&cth, g_cth);

    const int g1_smem = 2 * G1STAGE_B;   // 40960
    const int flash_smem = FSMEM_TOTAL;  // 46208 -> 2 CTAs/SM
    static int attrs_set = 0;
    if (!attrs_set) {
        cudaFuncSetAttribute(gemm1, cudaFuncAttributeMaxDynamicSharedMemorySize, g1_smem);
        cudaFuncSetAttribute(flash_mma, cudaFuncAttributeMaxDynamicSharedMemorySize, flash_smem);
        attrs_set = 1;
    }

    // 0) fp16 conversions
    {
        int n4x = (B_ * S_ * D_) / 4;
        split_hi<<<(n4x + 255) / 256, 256>>>(x, xh, n4x);
        int n4w = (3 * D_ * D_) / 4;
        split_hi<<<(n4w + 255) / 256, 256>>>(Wqkv, wqh, n4w);
        int n4o = (D_ * D_) / 4;
        split_hi<<<(n4o + 255) / 256, 256>>>(Wout, woh, n4o);
    }

    // 1) qkv = xh @ Wqkvh^T  (single 1-term GEMM, fp16 out)
    {
        dim3 grid((3 * D_) / 128, (B_ * S_) / 128);
        gemm1<<<grid, 256, g1_smem>>>(xh, wqh, nullptr, qvh, 3 * D_, D_, 1);
    }
    // 2) flash attention -> ctx fp16
    {
        dim3 grid(S_ / 64, B_ * H_);
        flash_mma<<<grid, 128, flash_smem>>>(qvh, mask, cth);
    }
    // 3) out = ctx @ Wout^T -> f32
    {
        dim3 grid(D_ / 128, (B_ * S_) / 128);
        gemm1<<<grid, 256, g1_smem>>>(cth, woh, out, nullptr, D_, D_, 0);
    }
}